// round 6
// baseline (speedup 1.0000x reference)
#include <cuda_runtime.h>
#include <cuda_fp16.h>
#include <math.h>
#include <stdint.h>

#define Bc 8
#define Sc 512
#define Dc 1024
#define Hc 16
#define HDc 64
#define FFc 4096
#define ROWS (Bc*Sc)
#define QS3 3072

__device__ float g_qkv[ROWS*(size_t)QS3];
__device__ float g_cache[ROWS*Dc];
__device__ __half g_hh[ROWS*Dc], g_h2h[ROWS*Dc], g_ctxh[ROWS*Dc];
__device__ __half g_ffh[ROWS*(size_t)FFc];
__device__ __half g_wqkv[(size_t)QS3*Dc];
__device__ __half g_wo[(size_t)Dc*Dc];
__device__ __half g_w1[(size_t)FFc*Dc];
__device__ __half g_w2[(size_t)Dc*FFc];

__device__ __forceinline__ uint32_t f2tf32(float f) {
    uint32_t u; asm("cvt.rna.tf32.f32 %0, %1;" : "=r"(u) : "f"(f)); return u;
}
__device__ __forceinline__ void mma_tf32(float (&d)[4], const uint32_t (&a)[4], const uint32_t (&b)[2]) {
    asm volatile("mma.sync.aligned.m16n8k8.row.col.f32.tf32.tf32.f32 "
        "{%0,%1,%2,%3}, {%4,%5,%6,%7}, {%8,%9}, {%0,%1,%2,%3};\n"
        : "+f"(d[0]), "+f"(d[1]), "+f"(d[2]), "+f"(d[3])
        : "r"(a[0]), "r"(a[1]), "r"(a[2]), "r"(a[3]), "r"(b[0]), "r"(b[1]));
}
__device__ __forceinline__ void mma_f16(float (&d)[4], const uint32_t (&a)[4], const uint32_t (&b)[2]) {
    asm volatile("mma.sync.aligned.m16n8k16.row.col.f32.f16.f16.f32 "
        "{%0,%1,%2,%3}, {%4,%5,%6,%7}, {%8,%9}, {%0,%1,%2,%3};\n"
        : "+f"(d[0]), "+f"(d[1]), "+f"(d[2]), "+f"(d[3])
        : "r"(a[0]), "r"(a[1]), "r"(a[2]), "r"(a[3]), "r"(b[0]), "r"(b[1]));
}

// ---------------------------------------------------------------------------
// Weight convert+transpose: fp32 [K][N] (slice z) -> fp16 [N][K]
// ---------------------------------------------------------------------------
__global__ __launch_bounds__(256) void convt_kernel(
    const float* __restrict__ in, __half* __restrict__ outp,
    int K, int N, int inZ, int outZrows, int Kout)
{
    __shared__ float tile[32][33];
    int k0 = blockIdx.y * 32, n0 = blockIdx.x * 32, z = blockIdx.z;
    const float* src = in + (size_t)z * inZ;
    int tx = threadIdx.x, ty = threadIdx.y;
    for (int j = ty; j < 32; j += 8)
        tile[j][tx] = src[(size_t)(k0 + j) * N + n0 + tx];
    __syncthreads();
    for (int j = ty; j < 32; j += 8) {
        size_t orow = (size_t)z * outZrows + n0 + j;
        outp[orow * Kout + k0 + tx] = __float2half_rn(tile[tx][j]);
    }
}

// ---------------------------------------------------------------------------
// LayerNorm -> fp16
// ---------------------------------------------------------------------------
__global__ __launch_bounds__(256) void ln_half_kernel(
    const float* __restrict__ x, const float* __restrict__ gamma,
    const float* __restrict__ beta, __half* __restrict__ outp)
{
    __shared__ float red[16];
    int row = blockIdx.x;
    float4 v = ((const float4*)(x + (size_t)row * Dc))[threadIdx.x];
    float s = v.x + v.y + v.z + v.w;
    float sq = v.x*v.x + v.y*v.y + v.z*v.z + v.w*v.w;
    #pragma unroll
    for (int off = 16; off; off >>= 1) {
        s  += __shfl_xor_sync(0xffffffffu, s,  off);
        sq += __shfl_xor_sync(0xffffffffu, sq, off);
    }
    int warp = threadIdx.x >> 5, lane = threadIdx.x & 31;
    if (lane == 0) { red[warp] = s; red[8 + warp] = sq; }
    __syncthreads();
    float ts = 0.f, tsq = 0.f;
    #pragma unroll
    for (int i = 0; i < 8; i++) { ts += red[i]; tsq += red[8 + i]; }
    float mean = ts * (1.0f / Dc);
    float inv = rsqrtf(tsq * (1.0f / Dc) - mean * mean + 1e-5f);
    float4 g4 = ((const float4*)gamma)[threadIdx.x];
    float4 b4 = ((const float4*)beta )[threadIdx.x];
    __half2 o[2];
    o[0] = __floats2half2_rn((v.x-mean)*inv*g4.x + b4.x, (v.y-mean)*inv*g4.y + b4.y);
    o[1] = __floats2half2_rn((v.z-mean)*inv*g4.z + b4.z, (v.w-mean)*inv*g4.w + b4.w);
    __half2* p = (__half2*)(outp + (size_t)row * Dc) + 2 * threadIdx.x;
    p[0] = o[0]; p[1] = o[1];
}

// ---------------------------------------------------------------------------
// fp16 GEMM: 128x128 block, BK=32, 256 threads = 8 warps (4M x 2N),
// warptile 32x64, mma m16n8k16, double-buffered smem, reg prefetch.
// A [M][K] fp16, B [N][K] fp16 (both K-major).
//  EPI 0: C fp32   EPI 1: C = acc + bias + resid (fp32)   EPI 2: gelu -> fp16
// ---------------------------------------------------------------------------
#define SSTR 20

template<int EPI>
__global__ __launch_bounds__(256) void gemm_f16(
    const __half* __restrict__ A, const __half* __restrict__ B,
    float* __restrict__ C, __half* __restrict__ Ch,
    const float* __restrict__ bias, const float* __restrict__ resid,
    int M, int N, int K)
{
    __shared__ uint32_t As[2][128 * SSTR];
    __shared__ uint32_t Bs[2][128 * SSTR];

    int m0 = blockIdx.y * 128, n0 = blockIdx.x * 128;
    int t = threadIdx.x;
    int w = t >> 5, lane = t & 31;
    int wm = w >> 1, wn = w & 1;
    int gid = lane >> 2, tid = lane & 3;

    float acc[2][8][4];
    #pragma unroll
    for (int mf = 0; mf < 2; mf++)
        #pragma unroll
        for (int nf = 0; nf < 8; nf++)
            #pragma unroll
            for (int c = 0; c < 4; c++) acc[mf][nf][c] = 0.f;

    int f0 = t, f1 = t + 256;   // float4 ids: row = f>>2, 8-half chunk = f&3
    float4 pa0, pa1, pb0, pb1;

    auto loadA = [&](int f, int k0) -> float4 {
        return *(const float4*)(A + (size_t)(m0 + (f >> 2)) * K + k0 + (f & 3) * 8);
    };
    auto loadB = [&](int f, int k0) -> float4 {
        return *(const float4*)(B + (size_t)(n0 + (f >> 2)) * K + k0 + (f & 3) * 8);
    };
    auto stash = [&](int buf) {
        *(uint4*)&As[buf][(f0 >> 2) * SSTR + (f0 & 3) * 4] = *(uint4*)&pa0;
        *(uint4*)&As[buf][(f1 >> 2) * SSTR + (f1 & 3) * 4] = *(uint4*)&pa1;
        *(uint4*)&Bs[buf][(f0 >> 2) * SSTR + (f0 & 3) * 4] = *(uint4*)&pb0;
        *(uint4*)&Bs[buf][(f1 >> 2) * SSTR + (f1 & 3) * 4] = *(uint4*)&pb1;
    };
    auto compute = [&](int buf) {
        #pragma unroll
        for (int ks = 0; ks < 2; ks++) {
            int kk = ks * 8;
            uint32_t afr[2][4], bfr[8][2];
            #pragma unroll
            for (int mf = 0; mf < 2; mf++) {
                int mb = wm * 32 + mf * 16 + gid;
                afr[mf][0] = As[buf][(mb    ) * SSTR + kk + tid];
                afr[mf][1] = As[buf][(mb + 8) * SSTR + kk + tid];
                afr[mf][2] = As[buf][(mb    ) * SSTR + kk + tid + 4];
                afr[mf][3] = As[buf][(mb + 8) * SSTR + kk + tid + 4];
            }
            #pragma unroll
            for (int nf = 0; nf < 8; nf++) {
                int nb = wn * 64 + nf * 8 + gid;
                bfr[nf][0] = Bs[buf][nb * SSTR + kk + tid];
                bfr[nf][1] = Bs[buf][nb * SSTR + kk + tid + 4];
            }
            #pragma unroll
            for (int mf = 0; mf < 2; mf++)
                #pragma unroll
                for (int nf = 0; nf < 8; nf++)
                    mma_f16(acc[mf][nf], afr[mf], bfr[nf]);
        }
    };

    pa0 = loadA(f0, 0); pa1 = loadA(f1, 0);
    pb0 = loadB(f0, 0); pb1 = loadB(f1, 0);
    stash(0);
    __syncthreads();

    int cur = 0;
    for (int k0 = 32; k0 < K; k0 += 32) {
        pa0 = loadA(f0, k0); pa1 = loadA(f1, k0);
        pb0 = loadB(f0, k0); pb1 = loadB(f1, k0);
        compute(cur);
        stash(cur ^ 1);
        __syncthreads();
        cur ^= 1;
    }
    compute(cur);

    #pragma unroll
    for (int mf = 0; mf < 2; mf++) {
        int r0 = m0 + wm * 32 + mf * 16 + gid;
        #pragma unroll
        for (int nf = 0; nf < 8; nf++) {
            int c0 = n0 + wn * 64 + nf * 8 + 2 * tid;
            float v0 = acc[mf][nf][0], v1 = acc[mf][nf][1];
            float v2 = acc[mf][nf][2], v3 = acc[mf][nf][3];
            if (EPI == 0) {
                *(float2*)(C + (size_t)r0 * N + c0)       = make_float2(v0, v1);
                *(float2*)(C + (size_t)(r0 + 8) * N + c0) = make_float2(v2, v3);
            } else if (EPI == 1) {
                float b0v = bias[c0], b1v = bias[c0 + 1];
                v0 += b0v + resid[(size_t)r0 * N + c0];
                v1 += b1v + resid[(size_t)r0 * N + c0 + 1];
                v2 += b0v + resid[(size_t)(r0 + 8) * N + c0];
                v3 += b1v + resid[(size_t)(r0 + 8) * N + c0 + 1];
                *(float2*)(C + (size_t)r0 * N + c0)       = make_float2(v0, v1);
                *(float2*)(C + (size_t)(r0 + 8) * N + c0) = make_float2(v2, v3);
            } else {
                float b0v = bias[c0], b1v = bias[c0 + 1];
                v0 += b0v; v1 += b1v; v2 += b0v; v3 += b1v;
                v0 = 0.5f * v0 * (1.0f + erff(v0 * 0.70710678118654752f));
                v1 = 0.5f * v1 * (1.0f + erff(v1 * 0.70710678118654752f));
                v2 = 0.5f * v2 * (1.0f + erff(v2 * 0.70710678118654752f));
                v3 = 0.5f * v3 * (1.0f + erff(v3 * 0.70710678118654752f));
                *(__half2*)(Ch + (size_t)r0 * N + c0)       = __floats2half2_rn(v0, v1);
                *(__half2*)(Ch + (size_t)(r0 + 8) * N + c0) = __floats2half2_rn(v2, v3);
            }
        }
    }
}

// ---------------------------------------------------------------------------
// Flash attention, tf32 mma. Reads fused qkv [row][3072] fp32, writes fp16 ctx.
// ---------------------------------------------------------------------------
#define AQ 68
#define ATTN_SMEM ((128 + 64 + 64 + 128) * AQ * 4)

__global__ __launch_bounds__(256) void attn_mma_kernel(
    const float* __restrict__ QKV, __half* __restrict__ Oh)
{
    extern __shared__ uint32_t smu[];
    uint32_t* sQ = smu;
    uint32_t* sK = sQ + 128 * AQ;
    uint32_t* sV = sK + 64 * AQ;
    uint32_t* sP = sV + 64 * AQ;

    int qt = blockIdx.x, hd = blockIdx.y, b = blockIdx.z;
    int t = threadIdx.x, w = t >> 5, lane = t & 31;
    int gid = lane >> 2, tid = lane & 3;
    size_t baseq = ((size_t)b * Sc) * QS3 + hd * HDc;
    size_t basek = baseq + 1024;
    size_t basev = baseq + 2048;
    size_t baseo = ((size_t)b * Sc) * Dc + hd * HDc;

    #pragma unroll
    for (int i = 0; i < 8; i++) {
        int f = t + i * 256, r = f >> 4, c4 = (f & 15) * 4;
        float4 v = *(const float4*)(QKV + baseq + (size_t)(qt * 128 + r) * QS3 + c4);
        uint4 u; u.x = f2tf32(v.x); u.y = f2tf32(v.y); u.z = f2tf32(v.z); u.w = f2tf32(v.w);
        *(uint4*)&sQ[r * AQ + c4] = u;
    }

    float m0r = -INFINITY, m1r = -INFINITY, l0 = 0.f, l1 = 0.f;
    float acc[8][4];
    #pragma unroll
    for (int nf = 0; nf < 8; nf++)
        #pragma unroll
        for (int c = 0; c < 4; c++) acc[nf][c] = 0.f;

    int row0 = qt * 128 + w * 16 + gid;
    int pr0 = (w * 16 + gid) * AQ, pr1 = (w * 16 + gid + 8) * AQ;

    int nt = 2 * qt + 2;
    for (int kt = 0; kt < nt; kt++) {
        #pragma unroll
        for (int i = 0; i < 4; i++) {
            int f = t + i * 256, r = f >> 4, c4 = (f & 15) * 4;
            float4 kv = *(const float4*)(QKV + basek + (size_t)(kt * 64 + r) * QS3 + c4);
            uint4 uk; uk.x = f2tf32(kv.x); uk.y = f2tf32(kv.y); uk.z = f2tf32(kv.z); uk.w = f2tf32(kv.w);
            *(uint4*)&sK[r * AQ + c4] = uk;
            float4 vv = *(const float4*)(QKV + basev + (size_t)(kt * 64 + r) * QS3 + c4);
            uint4 uv; uv.x = f2tf32(vv.x); uv.y = f2tf32(vv.y); uv.z = f2tf32(vv.z); uv.w = f2tf32(vv.w);
            *(uint4*)&sV[r * AQ + c4] = uv;
        }
        __syncthreads();

        float s[8][4];
        #pragma unroll
        for (int nf = 0; nf < 8; nf++)
            #pragma unroll
            for (int c = 0; c < 4; c++) s[nf][c] = 0.f;
        #pragma unroll
        for (int ks = 0; ks < 8; ks++) {
            int kk = ks * 8;
            uint32_t a[4] = { sQ[pr0 + kk + tid], sQ[pr1 + kk + tid],
                              sQ[pr0 + kk + tid + 4], sQ[pr1 + kk + tid + 4] };
            #pragma unroll
            for (int nf = 0; nf < 8; nf++) {
                uint32_t bb[2] = { sK[(nf * 8 + gid) * AQ + kk + tid],
                                   sK[(nf * 8 + gid) * AQ + kk + tid + 4] };
                mma_tf32(s[nf], a, bb);
            }
        }

        bool edge = (kt >= 2 * qt);
        #pragma unroll
        for (int nf = 0; nf < 8; nf++) {
            int c0 = kt * 64 + nf * 8 + 2 * tid;
            s[nf][0] *= 0.125f; s[nf][1] *= 0.125f;
            s[nf][2] *= 0.125f; s[nf][3] *= 0.125f;
            if (edge) {
                if (c0     > row0)     s[nf][0] = -1e10f;
                if (c0 + 1 > row0)     s[nf][1] = -1e10f;
                if (c0     > row0 + 8) s[nf][2] = -1e10f;
                if (c0 + 1 > row0 + 8) s[nf][3] = -1e10f;
            }
        }

        float mx0 = -INFINITY, mx1 = -INFINITY;
        #pragma unroll
        for (int nf = 0; nf < 8; nf++) {
            mx0 = fmaxf(mx0, fmaxf(s[nf][0], s[nf][1]));
            mx1 = fmaxf(mx1, fmaxf(s[nf][2], s[nf][3]));
        }
        mx0 = fmaxf(mx0, __shfl_xor_sync(0xffffffffu, mx0, 1));
        mx0 = fmaxf(mx0, __shfl_xor_sync(0xffffffffu, mx0, 2));
        mx1 = fmaxf(mx1, __shfl_xor_sync(0xffffffffu, mx1, 1));
        mx1 = fmaxf(mx1, __shfl_xor_sync(0xffffffffu, mx1, 2));
        float mn0 = fmaxf(m0r, mx0), mn1 = fmaxf(m1r, mx1);
        float corr0 = __expf(m0r - mn0), corr1 = __expf(m1r - mn1);
        float sum0 = 0.f, sum1 = 0.f;
        #pragma unroll
        for (int nf = 0; nf < 8; nf++) {
            s[nf][0] = __expf(s[nf][0] - mn0); sum0 += s[nf][0];
            s[nf][1] = __expf(s[nf][1] - mn0); sum0 += s[nf][1];
            s[nf][2] = __expf(s[nf][2] - mn1); sum1 += s[nf][2];
            s[nf][3] = __expf(s[nf][3] - mn1); sum1 += s[nf][3];
        }
        sum0 += __shfl_xor_sync(0xffffffffu, sum0, 1);
        sum0 += __shfl_xor_sync(0xffffffffu, sum0, 2);
        sum1 += __shfl_xor_sync(0xffffffffu, sum1, 1);
        sum1 += __shfl_xor_sync(0xffffffffu, sum1, 2);
        l0 = l0 * corr0 + sum0;  l1 = l1 * corr1 + sum1;
        m0r = mn0;  m1r = mn1;
        #pragma unroll
        for (int nf = 0; nf < 8; nf++) {
            acc[nf][0] *= corr0; acc[nf][1] *= corr0;
            acc[nf][2] *= corr1; acc[nf][3] *= corr1;
        }

        #pragma unroll
        for (int nf = 0; nf < 8; nf++) {
            int c = nf * 8 + 2 * tid;
            sP[pr0 + c]     = f2tf32(s[nf][0]);
            sP[pr0 + c + 1] = f2tf32(s[nf][1]);
            sP[pr1 + c]     = f2tf32(s[nf][2]);
            sP[pr1 + c + 1] = f2tf32(s[nf][3]);
        }
        __syncwarp();

        #pragma unroll
        for (int ks = 0; ks < 8; ks++) {
            int kk = ks * 8;
            uint32_t a[4] = { sP[pr0 + kk + tid], sP[pr1 + kk + tid],
                              sP[pr0 + kk + tid + 4], sP[pr1 + kk + tid + 4] };
            #pragma unroll
            for (int nf = 0; nf < 8; nf++) {
                uint32_t bb[2] = { sV[(kk + tid) * AQ + nf * 8 + gid],
                                   sV[(kk + tid + 4) * AQ + nf * 8 + gid] };
                mma_tf32(acc[nf], a, bb);
            }
        }
        __syncthreads();
    }

    float inv0 = 1.0f / l0, inv1 = 1.0f / l1;
    #pragma unroll
    for (int nf = 0; nf < 8; nf++) {
        int c = nf * 8 + 2 * tid;
        *(__half2*)(Oh + baseo + (size_t)(row0) * Dc + c) =
            __floats2half2_rn(acc[nf][0] * inv0, acc[nf][1] * inv0);
        *(__half2*)(Oh + baseo + (size_t)(row0 + 8) * Dc + c) =
            __floats2half2_rn(acc[nf][2] * inv1, acc[nf][3] * inv1);
    }
}

// ---------------------------------------------------------------------------
extern "C" void kernel_launch(void* const* d_in, const int* in_sizes, int n_in,
                              void* d_out, int out_size)
{
    const float* x   = (const float*)d_in[0];
    const float* Wq  = (const float*)d_in[1];
    const float* Wk  = (const float*)d_in[2];
    const float* Wv  = (const float*)d_in[3];
    const float* Wo  = (const float*)d_in[4];
    const float* bo  = (const float*)d_in[5];
    const float* g1  = (const float*)d_in[6];
    const float* b1  = (const float*)d_in[7];
    const float* g2  = (const float*)d_in[8];
    const float* b2  = (const float*)d_in[9];
    const float* W1  = (const float*)d_in[10];
    const float* bf1 = (const float*)d_in[11];
    const float* W2  = (const float*)d_in[12];
    const float* bf2 = (const float*)d_in[13];
    float* out = (float*)d_out;

    float *qkv, *cache;
    __half *hh, *h2h, *ctxh, *ffh, *wqkv, *wo, *w1, *w2;
    cudaGetSymbolAddress((void**)&qkv,   g_qkv);
    cudaGetSymbolAddress((void**)&cache, g_cache);
    cudaGetSymbolAddress((void**)&hh,    g_hh);
    cudaGetSymbolAddress((void**)&h2h,   g_h2h);
    cudaGetSymbolAddress((void**)&ctxh,  g_ctxh);
    cudaGetSymbolAddress((void**)&ffh,   g_ffh);
    cudaGetSymbolAddress((void**)&wqkv,  g_wqkv);
    cudaGetSymbolAddress((void**)&wo,    g_wo);
    cudaGetSymbolAddress((void**)&w1,    g_w1);
    cudaGetSymbolAddress((void**)&w2,    g_w2);

    cudaFuncSetAttribute(attn_mma_kernel, cudaFuncAttributeMaxDynamicSharedMemorySize, ATTN_SMEM);

    dim3 cb(32, 8);
    // Weights -> fp16 [N][K]; Q/K/V packed into one [3072][1024] buffer
    convt_kernel<<<dim3(2, 32, 16), cb>>>(Wq, wqkv,                          Dc, HDc, Dc * HDc, HDc, Dc);
    convt_kernel<<<dim3(2, 32, 16), cb>>>(Wk, wqkv + (size_t)1024 * Dc,      Dc, HDc, Dc * HDc, HDc, Dc);
    convt_kernel<<<dim3(2, 32, 16), cb>>>(Wv, wqkv + (size_t)2048 * Dc,      Dc, HDc, Dc * HDc, HDc, Dc);
    convt_kernel<<<dim3(32, 32, 1),  cb>>>(Wo, wo, Dc, Dc, 0, 0, Dc);
    convt_kernel<<<dim3(128, 32, 1), cb>>>(W1, w1, Dc, FFc, 0, 0, Dc);
    convt_kernel<<<dim3(32, 128, 1), cb>>>(W2, w2, FFc, Dc, 0, 0, FFc);

    // 1. LN1 -> fp16
    ln_half_kernel<<<ROWS, 256>>>(x, g1, b1, hh);

    // 2. Fused QKV projection (fp16 mma) -> qkv fp32 [ROWS][3072]
    gemm_f16<0><<<dim3(QS3 / 128, ROWS / 128), 256>>>(hh, wqkv, qkv, nullptr, nullptr, nullptr, ROWS, QS3, Dc);

    // 3. Attention (tf32 mma) -> ctx fp16
    attn_mma_kernel<<<dim3(Sc / 128, Hc, Bc), 256, ATTN_SMEM>>>(qkv, ctxh);

    // 4. Wo + bias + resid(x) -> cache fp32
    gemm_f16<1><<<dim3(Dc / 128, ROWS / 128), 256>>>(ctxh, wo, cache, nullptr, bo, x, ROWS, Dc, Dc);

    // 5. LN2 -> fp16
    ln_half_kernel<<<ROWS, 256>>>(cache, g2, b2, h2h);

    // 6. FF1 + bias + gelu -> ff fp16
    gemm_f16<2><<<dim3(FFc / 128, ROWS / 128), 256>>>(h2h, w1, nullptr, ffh, bf1, nullptr, ROWS, FFc, Dc);

    // 7. FF2 + bias + resid(cache) -> out fp32
    gemm_f16<1><<<dim3(Dc / 128, ROWS / 128), 256>>>(ffh, w2, out, nullptr, bf2, cache, ROWS, Dc, FFc);
}

// round 7
// speedup vs baseline: 1.6079x; 1.6079x over previous
#include <cuda_runtime.h>
#include <cuda_fp16.h>
#include <math.h>
#include <stdint.h>

#define Bc 8
#define Sc 512
#define Dc 1024
#define Hc 16
#define HDc 64
#define FFc 4096
#define ROWS (Bc*Sc)
#define QS3 3072

__device__ float g_qkv[ROWS*(size_t)QS3];
__device__ float g_cache[ROWS*Dc];
__device__ __half g_hh[ROWS*Dc], g_h2h[ROWS*Dc], g_ctxh[ROWS*Dc];
__device__ __half g_ffh[ROWS*(size_t)FFc];
__device__ __half g_wqkv[(size_t)QS3*Dc];
__device__ __half g_wo[(size_t)Dc*Dc];
__device__ __half g_w1[(size_t)FFc*Dc];
__device__ __half g_w2[(size_t)Dc*FFc];

__device__ __forceinline__ uint32_t smem_u32(const void* p) {
    uint32_t a;
    asm("{ .reg .u64 t; cvta.to.shared.u64 t, %1; cvt.u32.u64 %0, t; }" : "=r"(a) : "l"(p));
    return a;
}
__device__ __forceinline__ uint32_t f2tf32(float f) {
    uint32_t u; asm("cvt.rna.tf32.f32 %0, %1;" : "=r"(u) : "f"(f)); return u;
}
__device__ __forceinline__ void mma_tf32(float (&d)[4], const uint32_t (&a)[4], const uint32_t (&b)[2]) {
    asm volatile("mma.sync.aligned.m16n8k8.row.col.f32.tf32.tf32.f32 "
        "{%0,%1,%2,%3}, {%4,%5,%6,%7}, {%8,%9}, {%0,%1,%2,%3};\n"
        : "+f"(d[0]), "+f"(d[1]), "+f"(d[2]), "+f"(d[3])
        : "r"(a[0]), "r"(a[1]), "r"(a[2]), "r"(a[3]), "r"(b[0]), "r"(b[1]));
}
__device__ __forceinline__ void mma_f16(float (&d)[4], const uint32_t (&a)[4], const uint32_t (&b)[2]) {
    asm volatile("mma.sync.aligned.m16n8k16.row.col.f32.f16.f16.f32 "
        "{%0,%1,%2,%3}, {%4,%5,%6,%7}, {%8,%9}, {%0,%1,%2,%3};\n"
        : "+f"(d[0]), "+f"(d[1]), "+f"(d[2]), "+f"(d[3])
        : "r"(a[0]), "r"(a[1]), "r"(a[2]), "r"(a[3]), "r"(b[0]), "r"(b[1]));
}

// ---------------------------------------------------------------------------
// Weight convert+transpose: fp32 [K][N] (slice z) -> fp16 [N][K]
// ---------------------------------------------------------------------------
__global__ __launch_bounds__(256) void convt_kernel(
    const float* __restrict__ in, __half* __restrict__ outp,
    int K, int N, int inZ, int outZrows, int Kout)
{
    __shared__ float tile[32][33];
    int k0 = blockIdx.y * 32, n0 = blockIdx.x * 32, z = blockIdx.z;
    const float* src = in + (size_t)z * inZ;
    int tx = threadIdx.x, ty = threadIdx.y;
    for (int j = ty; j < 32; j += 8)
        tile[j][tx] = src[(size_t)(k0 + j) * N + n0 + tx];
    __syncthreads();
    for (int j = ty; j < 32; j += 8) {
        size_t orow = (size_t)z * outZrows + n0 + j;
        outp[orow * Kout + k0 + tx] = __float2half_rn(tile[tx][j]);
    }
}

// ---------------------------------------------------------------------------
// LayerNorm -> fp16
// ---------------------------------------------------------------------------
__global__ __launch_bounds__(256) void ln_half_kernel(
    const float* __restrict__ x, const float* __restrict__ gamma,
    const float* __restrict__ beta, __half* __restrict__ outp)
{
    __shared__ float red[16];
    int row = blockIdx.x;
    float4 v = ((const float4*)(x + (size_t)row * Dc))[threadIdx.x];
    float s = v.x + v.y + v.z + v.w;
    float sq = v.x*v.x + v.y*v.y + v.z*v.z + v.w*v.w;
    #pragma unroll
    for (int off = 16; off; off >>= 1) {
        s  += __shfl_xor_sync(0xffffffffu, s,  off);
        sq += __shfl_xor_sync(0xffffffffu, sq, off);
    }
    int warp = threadIdx.x >> 5, lane = threadIdx.x & 31;
    if (lane == 0) { red[warp] = s; red[8 + warp] = sq; }
    __syncthreads();
    float ts = 0.f, tsq = 0.f;
    #pragma unroll
    for (int i = 0; i < 8; i++) { ts += red[i]; tsq += red[8 + i]; }
    float mean = ts * (1.0f / Dc);
    float inv = rsqrtf(tsq * (1.0f / Dc) - mean * mean + 1e-5f);
    float4 g4 = ((const float4*)gamma)[threadIdx.x];
    float4 b4 = ((const float4*)beta )[threadIdx.x];
    __half2 o[2];
    o[0] = __floats2half2_rn((v.x-mean)*inv*g4.x + b4.x, (v.y-mean)*inv*g4.y + b4.y);
    o[1] = __floats2half2_rn((v.z-mean)*inv*g4.z + b4.z, (v.w-mean)*inv*g4.w + b4.w);
    __half2* p = (__half2*)(outp + (size_t)row * Dc) + 2 * threadIdx.x;
    p[0] = o[0]; p[1] = o[1];
}

// ---------------------------------------------------------------------------
// fp16 GEMM: 128x128 block, BK=32, 256 threads = 8 warps (4M x 2N),
// 3-stage cp.async pipeline, warptile 32x64, mma m16n8k16.
// A [M][K], B [N][K] fp16 K-major.
// smem row = 20 uint32 (80 B): frag LDS conflict-free, 16B-aligned chunks.
//  EPI 0: C fp32   EPI 1: C = acc + bias + resid (fp32)   EPI 2: gelu -> fp16
// ---------------------------------------------------------------------------
#define SSTR 20
#define STGU 2560                 // uint32 per stage buffer (128*20)
#define STGB (STGU*4)             // bytes
#define GSMEM (6 * STGB)          // 3 stages x (A+B) = 61440

template<int EPI>
__global__ __launch_bounds__(256) void gemm_f16(
    const __half* __restrict__ A, const __half* __restrict__ B,
    float* __restrict__ C, __half* __restrict__ Ch,
    const float* __restrict__ bias, const float* __restrict__ resid,
    int M, int N, int K)
{
    extern __shared__ __align__(16) char smem[];
    uint32_t* sw = (uint32_t*)smem;
    const uint32_t sbase = smem_u32(smem);

    int m0 = blockIdx.y * 128, n0 = blockIdx.x * 128;
    int t = threadIdx.x;
    int w = t >> 5, lane = t & 31;
    int wm = w >> 1, wn = w & 1;
    int gid = lane >> 2, tid = lane & 3;

    float acc[2][8][4];
    #pragma unroll
    for (int mf = 0; mf < 2; mf++)
        #pragma unroll
        for (int nf = 0; nf < 8; nf++)
            #pragma unroll
            for (int c = 0; c < 4; c++) acc[mf][nf][c] = 0.f;

    auto load_stage = [&](int s, int k0) {
        #pragma unroll
        for (int i = 0; i < 2; i++) {
            int id = t + i * 256;
            int row = id >> 2, kc = id & 3;
            uint32_t sa = sbase + s * STGB + row * 80 + kc * 16;
            const __half* ga = A + (size_t)(m0 + row) * K + k0 + kc * 8;
            asm volatile("cp.async.cg.shared.global [%0], [%1], 16;" :: "r"(sa), "l"(ga));
            uint32_t sb = sbase + 3 * STGB + s * STGB + row * 80 + kc * 16;
            const __half* gb = B + (size_t)(n0 + row) * K + k0 + kc * 8;
            asm volatile("cp.async.cg.shared.global [%0], [%1], 16;" :: "r"(sb), "l"(gb));
        }
        asm volatile("cp.async.commit_group;" ::: "memory");
    };

    const int NC = K / 32;
    load_stage(0, 0);
    load_stage(1, 32);

    int s = 0;
    for (int c = 0; c < NC; c++) {
        asm volatile("cp.async.wait_group 1;" ::: "memory");
        __syncthreads();
        if (c + 2 < NC) load_stage((s + 2) % 3, (c + 2) * 32);

        uint32_t* As = sw + s * STGU;
        uint32_t* Bs = sw + 3 * STGU + s * STGU;
        #pragma unroll
        for (int ks = 0; ks < 2; ks++) {
            int kk = ks * 8;
            uint32_t afr[2][4], bfr[8][2];
            #pragma unroll
            for (int mf = 0; mf < 2; mf++) {
                int mb = wm * 32 + mf * 16 + gid;
                afr[mf][0] = As[(mb    ) * SSTR + kk + tid];
                afr[mf][1] = As[(mb + 8) * SSTR + kk + tid];
                afr[mf][2] = As[(mb    ) * SSTR + kk + tid + 4];
                afr[mf][3] = As[(mb + 8) * SSTR + kk + tid + 4];
            }
            #pragma unroll
            for (int nf = 0; nf < 8; nf++) {
                int nb = wn * 64 + nf * 8 + gid;
                bfr[nf][0] = Bs[nb * SSTR + kk + tid];
                bfr[nf][1] = Bs[nb * SSTR + kk + tid + 4];
            }
            #pragma unroll
            for (int mf = 0; mf < 2; mf++)
                #pragma unroll
                for (int nf = 0; nf < 8; nf++)
                    mma_f16(acc[mf][nf], afr[mf], bfr[nf]);
        }
        __syncthreads();
        s = (s + 1) % 3;
    }

    #pragma unroll
    for (int mf = 0; mf < 2; mf++) {
        int r0 = m0 + wm * 32 + mf * 16 + gid;
        #pragma unroll
        for (int nf = 0; nf < 8; nf++) {
            int c0 = n0 + wn * 64 + nf * 8 + 2 * tid;
            float v0 = acc[mf][nf][0], v1 = acc[mf][nf][1];
            float v2 = acc[mf][nf][2], v3 = acc[mf][nf][3];
            if (EPI == 0) {
                *(float2*)(C + (size_t)r0 * N + c0)       = make_float2(v0, v1);
                *(float2*)(C + (size_t)(r0 + 8) * N + c0) = make_float2(v2, v3);
            } else if (EPI == 1) {
                float b0v = bias[c0], b1v = bias[c0 + 1];
                v0 += b0v + resid[(size_t)r0 * N + c0];
                v1 += b1v + resid[(size_t)r0 * N + c0 + 1];
                v2 += b0v + resid[(size_t)(r0 + 8) * N + c0];
                v3 += b1v + resid[(size_t)(r0 + 8) * N + c0 + 1];
                *(float2*)(C + (size_t)r0 * N + c0)       = make_float2(v0, v1);
                *(float2*)(C + (size_t)(r0 + 8) * N + c0) = make_float2(v2, v3);
            } else {
                float b0v = bias[c0], b1v = bias[c0 + 1];
                v0 += b0v; v1 += b1v; v2 += b0v; v3 += b1v;
                v0 = 0.5f * v0 * (1.0f + erff(v0 * 0.70710678118654752f));
                v1 = 0.5f * v1 * (1.0f + erff(v1 * 0.70710678118654752f));
                v2 = 0.5f * v2 * (1.0f + erff(v2 * 0.70710678118654752f));
                v3 = 0.5f * v3 * (1.0f + erff(v3 * 0.70710678118654752f));
                *(__half2*)(Ch + (size_t)r0 * N + c0)       = __floats2half2_rn(v0, v1);
                *(__half2*)(Ch + (size_t)(r0 + 8) * N + c0) = __floats2half2_rn(v2, v3);
            }
        }
    }
}

// ---------------------------------------------------------------------------
// Flash attention, tf32 mma. Reads fused qkv [row][3072] fp32, writes fp16 ctx.
// ---------------------------------------------------------------------------
#define AQ 68
#define ATTN_SMEM ((128 + 64 + 64 + 128) * AQ * 4)

__global__ __launch_bounds__(256) void attn_mma_kernel(
    const float* __restrict__ QKV, __half* __restrict__ Oh)
{
    extern __shared__ uint32_t smu[];
    uint32_t* sQ = smu;
    uint32_t* sK = sQ + 128 * AQ;
    uint32_t* sV = sK + 64 * AQ;
    uint32_t* sP = sV + 64 * AQ;

    int qt = blockIdx.x, hd = blockIdx.y, b = blockIdx.z;
    int t = threadIdx.x, w = t >> 5, lane = t & 31;
    int gid = lane >> 2, tid = lane & 3;
    size_t baseq = ((size_t)b * Sc) * QS3 + hd * HDc;
    size_t basek = baseq + 1024;
    size_t basev = baseq + 2048;
    size_t baseo = ((size_t)b * Sc) * Dc + hd * HDc;

    #pragma unroll
    for (int i = 0; i < 8; i++) {
        int f = t + i * 256, r = f >> 4, c4 = (f & 15) * 4;
        float4 v = *(const float4*)(QKV + baseq + (size_t)(qt * 128 + r) * QS3 + c4);
        uint4 u; u.x = f2tf32(v.x); u.y = f2tf32(v.y); u.z = f2tf32(v.z); u.w = f2tf32(v.w);
        *(uint4*)&sQ[r * AQ + c4] = u;
    }

    float m0r = -INFINITY, m1r = -INFINITY, l0 = 0.f, l1 = 0.f;
    float acc[8][4];
    #pragma unroll
    for (int nf = 0; nf < 8; nf++)
        #pragma unroll
        for (int c = 0; c < 4; c++) acc[nf][c] = 0.f;

    int row0 = qt * 128 + w * 16 + gid;
    int pr0 = (w * 16 + gid) * AQ, pr1 = (w * 16 + gid + 8) * AQ;

    int nt = 2 * qt + 2;
    for (int kt = 0; kt < nt; kt++) {
        #pragma unroll
        for (int i = 0; i < 4; i++) {
            int f = t + i * 256, r = f >> 4, c4 = (f & 15) * 4;
            float4 kv = *(const float4*)(QKV + basek + (size_t)(kt * 64 + r) * QS3 + c4);
            uint4 uk; uk.x = f2tf32(kv.x); uk.y = f2tf32(kv.y); uk.z = f2tf32(kv.z); uk.w = f2tf32(kv.w);
            *(uint4*)&sK[r * AQ + c4] = uk;
            float4 vv = *(const float4*)(QKV + basev + (size_t)(kt * 64 + r) * QS3 + c4);
            uint4 uv; uv.x = f2tf32(vv.x); uv.y = f2tf32(vv.y); uv.z = f2tf32(vv.z); uv.w = f2tf32(vv.w);
            *(uint4*)&sV[r * AQ + c4] = uv;
        }
        __syncthreads();

        float s[8][4];
        #pragma unroll
        for (int nf = 0; nf < 8; nf++)
            #pragma unroll
            for (int c = 0; c < 4; c++) s[nf][c] = 0.f;
        #pragma unroll
        for (int ks = 0; ks < 8; ks++) {
            int kk = ks * 8;
            uint32_t a[4] = { sQ[pr0 + kk + tid], sQ[pr1 + kk + tid],
                              sQ[pr0 + kk + tid + 4], sQ[pr1 + kk + tid + 4] };
            #pragma unroll
            for (int nf = 0; nf < 8; nf++) {
                uint32_t bb[2] = { sK[(nf * 8 + gid) * AQ + kk + tid],
                                   sK[(nf * 8 + gid) * AQ + kk + tid + 4] };
                mma_tf32(s[nf], a, bb);
            }
        }

        bool edge = (kt >= 2 * qt);
        #pragma unroll
        for (int nf = 0; nf < 8; nf++) {
            int c0 = kt * 64 + nf * 8 + 2 * tid;
            s[nf][0] *= 0.125f; s[nf][1] *= 0.125f;
            s[nf][2] *= 0.125f; s[nf][3] *= 0.125f;
            if (edge) {
                if (c0     > row0)     s[nf][0] = -1e10f;
                if (c0 + 1 > row0)     s[nf][1] = -1e10f;
                if (c0     > row0 + 8) s[nf][2] = -1e10f;
                if (c0 + 1 > row0 + 8) s[nf][3] = -1e10f;
            }
        }

        float mx0 = -INFINITY, mx1 = -INFINITY;
        #pragma unroll
        for (int nf = 0; nf < 8; nf++) {
            mx0 = fmaxf(mx0, fmaxf(s[nf][0], s[nf][1]));
            mx1 = fmaxf(mx1, fmaxf(s[nf][2], s[nf][3]));
        }
        mx0 = fmaxf(mx0, __shfl_xor_sync(0xffffffffu, mx0, 1));
        mx0 = fmaxf(mx0, __shfl_xor_sync(0xffffffffu, mx0, 2));
        mx1 = fmaxf(mx1, __shfl_xor_sync(0xffffffffu, mx1, 1));
        mx1 = fmaxf(mx1, __shfl_xor_sync(0xffffffffu, mx1, 2));
        float mn0 = fmaxf(m0r, mx0), mn1 = fmaxf(m1r, mx1);
        float corr0 = __expf(m0r - mn0), corr1 = __expf(m1r - mn1);
        float sum0 = 0.f, sum1 = 0.f;
        #pragma unroll
        for (int nf = 0; nf < 8; nf++) {
            s[nf][0] = __expf(s[nf][0] - mn0); sum0 += s[nf][0];
            s[nf][1] = __expf(s[nf][1] - mn0); sum0 += s[nf][1];
            s[nf][2] = __expf(s[nf][2] - mn1); sum1 += s[nf][2];
            s[nf][3] = __expf(s[nf][3] - mn1); sum1 += s[nf][3];
        }
        sum0 += __shfl_xor_sync(0xffffffffu, sum0, 1);
        sum0 += __shfl_xor_sync(0xffffffffu, sum0, 2);
        sum1 += __shfl_xor_sync(0xffffffffu, sum1, 1);
        sum1 += __shfl_xor_sync(0xffffffffu, sum1, 2);
        l0 = l0 * corr0 + sum0;  l1 = l1 * corr1 + sum1;
        m0r = mn0;  m1r = mn1;
        #pragma unroll
        for (int nf = 0; nf < 8; nf++) {
            acc[nf][0] *= corr0; acc[nf][1] *= corr0;
            acc[nf][2] *= corr1; acc[nf][3] *= corr1;
        }

        #pragma unroll
        for (int nf = 0; nf < 8; nf++) {
            int c = nf * 8 + 2 * tid;
            sP[pr0 + c]     = f2tf32(s[nf][0]);
            sP[pr0 + c + 1] = f2tf32(s[nf][1]);
            sP[pr1 + c]     = f2tf32(s[nf][2]);
            sP[pr1 + c + 1] = f2tf32(s[nf][3]);
        }
        __syncwarp();

        #pragma unroll
        for (int ks = 0; ks < 8; ks++) {
            int kk = ks * 8;
            uint32_t a[4] = { sP[pr0 + kk + tid], sP[pr1 + kk + tid],
                              sP[pr0 + kk + tid + 4], sP[pr1 + kk + tid + 4] };
            #pragma unroll
            for (int nf = 0; nf < 8; nf++) {
                uint32_t bb[2] = { sV[(kk + tid) * AQ + nf * 8 + gid],
                                   sV[(kk + tid + 4) * AQ + nf * 8 + gid] };
                mma_tf32(acc[nf], a, bb);
            }
        }
        __syncthreads();
    }

    float inv0 = 1.0f / l0, inv1 = 1.0f / l1;
    #pragma unroll
    for (int nf = 0; nf < 8; nf++) {
        int c = nf * 8 + 2 * tid;
        *(__half2*)(Oh + baseo + (size_t)(row0) * Dc + c) =
            __floats2half2_rn(acc[nf][0] * inv0, acc[nf][1] * inv0);
        *(__half2*)(Oh + baseo + (size_t)(row0 + 8) * Dc + c) =
            __floats2half2_rn(acc[nf][2] * inv1, acc[nf][3] * inv1);
    }
}

// ---------------------------------------------------------------------------
extern "C" void kernel_launch(void* const* d_in, const int* in_sizes, int n_in,
                              void* d_out, int out_size)
{
    const float* x   = (const float*)d_in[0];
    const float* Wq  = (const float*)d_in[1];
    const float* Wk  = (const float*)d_in[2];
    const float* Wv  = (const float*)d_in[3];
    const float* Wo  = (const float*)d_in[4];
    const float* bo  = (const float*)d_in[5];
    const float* g1  = (const float*)d_in[6];
    const float* b1  = (const float*)d_in[7];
    const float* g2  = (const float*)d_in[8];
    const float* b2  = (const float*)d_in[9];
    const float* W1  = (const float*)d_in[10];
    const float* bf1 = (const float*)d_in[11];
    const float* W2  = (const float*)d_in[12];
    const float* bf2 = (const float*)d_in[13];
    float* out = (float*)d_out;

    float *qkv, *cache;
    __half *hh, *h2h, *ctxh, *ffh, *wqkv, *wo, *w1, *w2;
    cudaGetSymbolAddress((void**)&qkv,   g_qkv);
    cudaGetSymbolAddress((void**)&cache, g_cache);
    cudaGetSymbolAddress((void**)&hh,    g_hh);
    cudaGetSymbolAddress((void**)&h2h,   g_h2h);
    cudaGetSymbolAddress((void**)&ctxh,  g_ctxh);
    cudaGetSymbolAddress((void**)&ffh,   g_ffh);
    cudaGetSymbolAddress((void**)&wqkv,  g_wqkv);
    cudaGetSymbolAddress((void**)&wo,    g_wo);
    cudaGetSymbolAddress((void**)&w1,    g_w1);
    cudaGetSymbolAddress((void**)&w2,    g_w2);

    cudaFuncSetAttribute(gemm_f16<0>, cudaFuncAttributeMaxDynamicSharedMemorySize, GSMEM);
    cudaFuncSetAttribute(gemm_f16<1>, cudaFuncAttributeMaxDynamicSharedMemorySize, GSMEM);
    cudaFuncSetAttribute(gemm_f16<2>, cudaFuncAttributeMaxDynamicSharedMemorySize, GSMEM);
    cudaFuncSetAttribute(attn_mma_kernel, cudaFuncAttributeMaxDynamicSharedMemorySize, ATTN_SMEM);

    dim3 cb(32, 8);
    convt_kernel<<<dim3(2, 32, 16), cb>>>(Wq, wqkv,                     Dc, HDc, Dc * HDc, HDc, Dc);
    convt_kernel<<<dim3(2, 32, 16), cb>>>(Wk, wqkv + (size_t)1024 * Dc, Dc, HDc, Dc * HDc, HDc, Dc);
    convt_kernel<<<dim3(2, 32, 16), cb>>>(Wv, wqkv + (size_t)2048 * Dc, Dc, HDc, Dc * HDc, HDc, Dc);
    convt_kernel<<<dim3(32, 32, 1),  cb>>>(Wo, wo, Dc, Dc, 0, 0, Dc);
    convt_kernel<<<dim3(128, 32, 1), cb>>>(W1, w1, Dc, FFc, 0, 0, Dc);
    convt_kernel<<<dim3(32, 128, 1), cb>>>(W2, w2, FFc, Dc, 0, 0, FFc);

    // 1. LN1 -> fp16
    ln_half_kernel<<<ROWS, 256>>>(x, g1, b1, hh);

    // 2. Fused QKV projection -> qkv fp32 [ROWS][3072]
    gemm_f16<0><<<dim3(QS3 / 128, ROWS / 128), 256, GSMEM>>>(hh, wqkv, qkv, nullptr, nullptr, nullptr, ROWS, QS3, Dc);

    // 3. Attention -> ctx fp16
    attn_mma_kernel<<<dim3(Sc / 128, Hc, Bc), 256, ATTN_SMEM>>>(qkv, ctxh);

    // 4. Wo + bias + resid(x) -> cache fp32
    gemm_f16<1><<<dim3(Dc / 128, ROWS / 128), 256, GSMEM>>>(ctxh, wo, cache, nullptr, bo, x, ROWS, Dc, Dc);

    // 5. LN2 -> fp16
    ln_half_kernel<<<ROWS, 256>>>(cache, g2, b2, h2h);

    // 6. FF1 + bias + gelu -> ff fp16
    gemm_f16<2><<<dim3(FFc / 128, ROWS / 128), 256, GSMEM>>>(h2h, w1, nullptr, ffh, bf1, nullptr, ROWS, FFc, Dc);

    // 7. FF2 + bias + resid(cache) -> out fp32
    gemm_f16<1><<<dim3(Dc / 128, ROWS / 128), 256, GSMEM>>>(ffh, w2, out, nullptr, bf2, cache, ROWS, Dc, FFc);
}

// round 9
// speedup vs baseline: 1.7165x; 1.0676x over previous
#include <cuda_runtime.h>
#include <cuda_fp16.h>
#include <math.h>
#include <stdint.h>

#define Bc 8
#define Sc 512
#define Dc 1024
#define Hc 16
#define HDc 64
#define FFc 4096
#define ROWS (Bc*Sc)
#define QS3 3072

__device__ __half g_qkv[ROWS*(size_t)QS3];
__device__ float g_cache[ROWS*Dc];
__device__ __half g_hh[ROWS*Dc], g_h2h[ROWS*Dc], g_ctxh[ROWS*Dc];
__device__ __half g_ffh[ROWS*(size_t)FFc];
__device__ __half g_wqkv[(size_t)QS3*Dc];
__device__ __half g_wo[(size_t)Dc*Dc];
__device__ __half g_w1[(size_t)FFc*Dc];
__device__ __half g_w2[(size_t)Dc*FFc];

__device__ __forceinline__ uint32_t smem_u32(const void* p) {
    uint32_t a;
    asm("{ .reg .u64 t; cvta.to.shared.u64 t, %1; cvt.u32.u64 %0, t; }" : "=r"(a) : "l"(p));
    return a;
}
__device__ __forceinline__ void mma_f16(float (&d)[4], const uint32_t (&a)[4], const uint32_t (&b)[2]) {
    asm volatile("mma.sync.aligned.m16n8k16.row.col.f32.f16.f16.f32 "
        "{%0,%1,%2,%3}, {%4,%5,%6,%7}, {%8,%9}, {%0,%1,%2,%3};\n"
        : "+f"(d[0]), "+f"(d[1]), "+f"(d[2]), "+f"(d[3])
        : "r"(a[0]), "r"(a[1]), "r"(a[2]), "r"(a[3]), "r"(b[0]), "r"(b[1]));
}

// ---------------------------------------------------------------------------
// Weight convert+transpose: fp32 [K][N] (slice z) -> fp16 [N][K]
// ---------------------------------------------------------------------------
__global__ __launch_bounds__(256) void convt_kernel(
    const float* __restrict__ in, __half* __restrict__ outp,
    int K, int N, int inZ, int outZrows, int Kout)
{
    __shared__ float tile[32][33];
    int k0 = blockIdx.y * 32, n0 = blockIdx.x * 32, z = blockIdx.z;
    const float* src = in + (size_t)z * inZ;
    int tx = threadIdx.x, ty = threadIdx.y;
    for (int j = ty; j < 32; j += 8)
        tile[j][tx] = src[(size_t)(k0 + j) * N + n0 + tx];
    __syncthreads();
    for (int j = ty; j < 32; j += 8) {
        size_t orow = (size_t)z * outZrows + n0 + j;
        outp[orow * Kout + k0 + tx] = __float2half_rn(tile[tx][j]);
    }
}

// ---------------------------------------------------------------------------
// LayerNorm -> fp16
// ---------------------------------------------------------------------------
__global__ __launch_bounds__(256) void ln_half_kernel(
    const float* __restrict__ x, const float* __restrict__ gamma,
    const float* __restrict__ beta, __half* __restrict__ outp)
{
    __shared__ float red[16];
    int row = blockIdx.x;
    float4 v = ((const float4*)(x + (size_t)row * Dc))[threadIdx.x];
    float s = v.x + v.y + v.z + v.w;
    float sq = v.x*v.x + v.y*v.y + v.z*v.z + v.w*v.w;
    #pragma unroll
    for (int off = 16; off; off >>= 1) {
        s  += __shfl_xor_sync(0xffffffffu, s,  off);
        sq += __shfl_xor_sync(0xffffffffu, sq, off);
    }
    int warp = threadIdx.x >> 5, lane = threadIdx.x & 31;
    if (lane == 0) { red[warp] = s; red[8 + warp] = sq; }
    __syncthreads();
    float ts = 0.f, tsq = 0.f;
    #pragma unroll
    for (int i = 0; i < 8; i++) { ts += red[i]; tsq += red[8 + i]; }
    float mean = ts * (1.0f / Dc);
    float inv = rsqrtf(tsq * (1.0f / Dc) - mean * mean + 1e-5f);
    float4 g4 = ((const float4*)gamma)[threadIdx.x];
    float4 b4 = ((const float4*)beta )[threadIdx.x];
    __half2 o[2];
    o[0] = __floats2half2_rn((v.x-mean)*inv*g4.x + b4.x, (v.y-mean)*inv*g4.y + b4.y);
    o[1] = __floats2half2_rn((v.z-mean)*inv*g4.z + b4.z, (v.w-mean)*inv*g4.w + b4.w);
    __half2* p = (__half2*)(outp + (size_t)row * Dc) + 2 * threadIdx.x;
    p[0] = o[0]; p[1] = o[1];
}

// ---------------------------------------------------------------------------
// fp16 GEMM: 128x128 block, BK=32, 4-stage cp.async pipeline, ONE barrier
// per k-chunk. 256 threads = 8 warps (4M x 2N), warptile 32x64, m16n8k16.
//  EPI 0: C fp32   EPI 1: acc+bias+resid fp32   EPI 2: gelu->fp16   EPI 3: fp16
// ---------------------------------------------------------------------------
#define SSTR 20
#define STGU 2560
#define STGB (STGU*4)
#define GSMEM (8 * STGB)   // 4 stages x (A+B) = 81920

template<int EPI>
__global__ __launch_bounds__(256) void gemm_f16(
    const __half* __restrict__ A, const __half* __restrict__ B,
    float* __restrict__ C, __half* __restrict__ Ch,
    const float* __restrict__ bias, const float* __restrict__ resid,
    int M, int N, int K)
{
    extern __shared__ __align__(16) char smem[];
    uint32_t* sw = (uint32_t*)smem;
    const uint32_t sbase = smem_u32(smem);

    int m0 = blockIdx.y * 128, n0 = blockIdx.x * 128;
    int t = threadIdx.x;
    int w = t >> 5, lane = t & 31;
    int wm = w >> 1, wn = w & 1;
    int gid = lane >> 2, tid = lane & 3;

    float acc[2][8][4];
    #pragma unroll
    for (int mf = 0; mf < 2; mf++)
        #pragma unroll
        for (int nf = 0; nf < 8; nf++)
            #pragma unroll
            for (int c = 0; c < 4; c++) acc[mf][nf][c] = 0.f;

    auto load_stage = [&](int s, int k0) {
        #pragma unroll
        for (int i = 0; i < 2; i++) {
            int id = t + i * 256;
            int row = id >> 2, kc = id & 3;
            uint32_t sa = sbase + s * STGB + row * 80 + kc * 16;
            const __half* ga = A + (size_t)(m0 + row) * K + k0 + kc * 8;
            asm volatile("cp.async.cg.shared.global [%0], [%1], 16;" :: "r"(sa), "l"(ga));
            uint32_t sb = sbase + 4 * STGB + s * STGB + row * 80 + kc * 16;
            const __half* gb = B + (size_t)(n0 + row) * K + k0 + kc * 8;
            asm volatile("cp.async.cg.shared.global [%0], [%1], 16;" :: "r"(sb), "l"(gb));
        }
        asm volatile("cp.async.commit_group;" ::: "memory");
    };

    const int NC = K / 32;
    load_stage(0, 0);
    load_stage(1, 32);
    load_stage(2, 64);

    int s = 0;
    for (int c = 0; c < NC; c++) {
        asm volatile("cp.async.wait_group 2;" ::: "memory");
        __syncthreads();
        if (c + 3 < NC) load_stage((s + 3) & 3, (c + 3) * 32);

        uint32_t* As = sw + s * STGU;
        uint32_t* Bs = sw + 4 * STGU + s * STGU;
        #pragma unroll
        for (int ks = 0; ks < 2; ks++) {
            int kk = ks * 8;
            uint32_t afr[2][4], bfr[8][2];
            #pragma unroll
            for (int mf = 0; mf < 2; mf++) {
                int mb = wm * 32 + mf * 16 + gid;
                afr[mf][0] = As[(mb    ) * SSTR + kk + tid];
                afr[mf][1] = As[(mb + 8) * SSTR + kk + tid];
                afr[mf][2] = As[(mb    ) * SSTR + kk + tid + 4];
                afr[mf][3] = As[(mb + 8) * SSTR + kk + tid + 4];
            }
            #pragma unroll
            for (int nf = 0; nf < 8; nf++) {
                int nb = wn * 64 + nf * 8 + gid;
                bfr[nf][0] = Bs[nb * SSTR + kk + tid];
                bfr[nf][1] = Bs[nb * SSTR + kk + tid + 4];
            }
            #pragma unroll
            for (int mf = 0; mf < 2; mf++)
                #pragma unroll
                for (int nf = 0; nf < 8; nf++)
                    mma_f16(acc[mf][nf], afr[mf], bfr[nf]);
        }
        s = (s + 1) & 3;
    }

    #pragma unroll
    for (int mf = 0; mf < 2; mf++) {
        int r0 = m0 + wm * 32 + mf * 16 + gid;
        #pragma unroll
        for (int nf = 0; nf < 8; nf++) {
            int c0 = n0 + wn * 64 + nf * 8 + 2 * tid;
            float v0 = acc[mf][nf][0], v1 = acc[mf][nf][1];
            float v2 = acc[mf][nf][2], v3 = acc[mf][nf][3];
            if (EPI == 0) {
                *(float2*)(C + (size_t)r0 * N + c0)       = make_float2(v0, v1);
                *(float2*)(C + (size_t)(r0 + 8) * N + c0) = make_float2(v2, v3);
            } else if (EPI == 1) {
                float b0v = bias[c0], b1v = bias[c0 + 1];
                v0 += b0v + resid[(size_t)r0 * N + c0];
                v1 += b1v + resid[(size_t)r0 * N + c0 + 1];
                v2 += b0v + resid[(size_t)(r0 + 8) * N + c0];
                v3 += b1v + resid[(size_t)(r0 + 8) * N + c0 + 1];
                *(float2*)(C + (size_t)r0 * N + c0)       = make_float2(v0, v1);
                *(float2*)(C + (size_t)(r0 + 8) * N + c0) = make_float2(v2, v3);
            } else if (EPI == 2) {
                float b0v = bias[c0], b1v = bias[c0 + 1];
                v0 += b0v; v1 += b1v; v2 += b0v; v3 += b1v;
                v0 = 0.5f * v0 * (1.0f + erff(v0 * 0.70710678118654752f));
                v1 = 0.5f * v1 * (1.0f + erff(v1 * 0.70710678118654752f));
                v2 = 0.5f * v2 * (1.0f + erff(v2 * 0.70710678118654752f));
                v3 = 0.5f * v3 * (1.0f + erff(v3 * 0.70710678118654752f));
                *(__half2*)(Ch + (size_t)r0 * N + c0)       = __floats2half2_rn(v0, v1);
                *(__half2*)(Ch + (size_t)(r0 + 8) * N + c0) = __floats2half2_rn(v2, v3);
            } else {
                *(__half2*)(Ch + (size_t)r0 * N + c0)       = __floats2half2_rn(v0, v1);
                *(__half2*)(Ch + (size_t)(r0 + 8) * N + c0) = __floats2half2_rn(v2, v3);
            }
        }
    }
}

// ---------------------------------------------------------------------------
// Flash attention, fp16 mma (m16n8k16). qkv fp16 [row][3072]. ctx fp16 out.
// smem word rows: stride 36 (32 data words = 64 halves + pad 4) ->
//   frag LDS banks = 4*gid + tid (+k) : conflict-free.
// V stored transposed as half2 pairs at load (lane = kv-pair -> conflict-free STS).
// ---------------------------------------------------------------------------
#define AVST 36
#define ATTN_SMEM ((128 + 64 + 64 + 128) * AVST * 4)   // 55296 B

__global__ __launch_bounds__(256) void attn_mma_kernel(
    const __half* __restrict__ QKV, __half* __restrict__ Oh)
{
    extern __shared__ uint32_t smu[];
    uint32_t* sQ  = smu;                     // [128][AVST] halves along e
    uint32_t* sK  = sQ  + 128 * AVST;        // [64][AVST]  halves along e
    uint32_t* sVt = sK  + 64 * AVST;         // [64 e][AVST] halves along kv (transposed)
    uint32_t* sP  = sVt + 64 * AVST;         // [128][AVST] halves along kv

    int qt = blockIdx.x, hd = blockIdx.y, b = blockIdx.z;
    int t = threadIdx.x, w = t >> 5, lane = t & 31;
    int gid = lane >> 2, tid = lane & 3;
    size_t baseq = ((size_t)b * Sc) * QS3 + hd * HDc;
    size_t basek = baseq + 1024;
    size_t basev = baseq + 2048;
    size_t baseo = ((size_t)b * Sc) * Dc + hd * HDc;

    // Q tile: 128 rows x 64 halves
    #pragma unroll
    for (int i = 0; i < 4; i++) {
        int f = t + i * 256, r = f >> 3, c8 = f & 7;
        uint4 u = *(const uint4*)(QKV + baseq + (size_t)(qt * 128 + r) * QS3 + c8 * 8);
        *(uint4*)&sQ[r * AVST + c8 * 4] = u;
    }

    float m0r = -INFINITY, m1r = -INFINITY, l0 = 0.f, l1 = 0.f;
    float acc[8][4];
    #pragma unroll
    for (int nf = 0; nf < 8; nf++)
        #pragma unroll
        for (int c = 0; c < 4; c++) acc[nf][c] = 0.f;

    int row0 = qt * 128 + w * 16 + gid;
    int pr0 = (w * 16 + gid) * AVST, pr1 = (w * 16 + gid + 8) * AVST;

    int vrp = t & 31, vcg = (t >> 5) * 8;    // V-transpose mapping

    int nt = 2 * qt + 2;
    for (int kt = 0; kt < nt; kt++) {
        // K tile
        #pragma unroll
        for (int i = 0; i < 2; i++) {
            int f = t + i * 256, r = f >> 3, c8 = f & 7;
            uint4 u = *(const uint4*)(QKV + basek + (size_t)(kt * 64 + r) * QS3 + c8 * 8);
            *(uint4*)&sK[r * AVST + c8 * 4] = u;
        }
        // V tile transposed: pair rows (2*vrp, 2*vrp+1), cols vcg..vcg+7
        {
            const __half* v0p = QKV + basev + (size_t)(kt * 64 + 2 * vrp) * QS3 + vcg;
            uint4 u0 = *(const uint4*)(v0p);
            uint4 u1 = *(const uint4*)(v0p + QS3);
            const __half* h0 = (const __half*)&u0;
            const __half* h1 = (const __half*)&u1;
            #pragma unroll
            for (int i = 0; i < 8; i++) {
                __half2 hv; hv.x = h0[i]; hv.y = h1[i];
                sVt[(vcg + i) * AVST + vrp] = *(uint32_t*)&hv;
            }
        }
        __syncthreads();

        // S = Q @ K^T  (e = 64 -> 4 k16 steps)
        float s[8][4];
        #pragma unroll
        for (int nf = 0; nf < 8; nf++)
            #pragma unroll
            for (int c = 0; c < 4; c++) s[nf][c] = 0.f;
        #pragma unroll
        for (int ks = 0; ks < 4; ks++) {
            int kk = ks * 8;
            uint32_t a[4] = { sQ[pr0 + kk + tid], sQ[pr1 + kk + tid],
                              sQ[pr0 + kk + tid + 4], sQ[pr1 + kk + tid + 4] };
            #pragma unroll
            for (int nf = 0; nf < 8; nf++) {
                uint32_t bb[2] = { sK[(nf * 8 + gid) * AVST + kk + tid],
                                   sK[(nf * 8 + gid) * AVST + kk + tid + 4] };
                mma_f16(s[nf], a, bb);
            }
        }

        bool edge = (kt >= 2 * qt);
        #pragma unroll
        for (int nf = 0; nf < 8; nf++) {
            int c0 = kt * 64 + nf * 8 + 2 * tid;
            s[nf][0] *= 0.125f; s[nf][1] *= 0.125f;
            s[nf][2] *= 0.125f; s[nf][3] *= 0.125f;
            if (edge) {
                if (c0     > row0)     s[nf][0] = -1e10f;
                if (c0 + 1 > row0)     s[nf][1] = -1e10f;
                if (c0     > row0 + 8) s[nf][2] = -1e10f;
                if (c0 + 1 > row0 + 8) s[nf][3] = -1e10f;
            }
        }

        float mx0 = -INFINITY, mx1 = -INFINITY;
        #pragma unroll
        for (int nf = 0; nf < 8; nf++) {
            mx0 = fmaxf(mx0, fmaxf(s[nf][0], s[nf][1]));
            mx1 = fmaxf(mx1, fmaxf(s[nf][2], s[nf][3]));
        }
        mx0 = fmaxf(mx0, __shfl_xor_sync(0xffffffffu, mx0, 1));
        mx0 = fmaxf(mx0, __shfl_xor_sync(0xffffffffu, mx0, 2));
        mx1 = fmaxf(mx1, __shfl_xor_sync(0xffffffffu, mx1, 1));
        mx1 = fmaxf(mx1, __shfl_xor_sync(0xffffffffu, mx1, 2));
        float mn0 = fmaxf(m0r, mx0), mn1 = fmaxf(m1r, mx1);
        float corr0 = __expf(m0r - mn0), corr1 = __expf(m1r - mn1);
        float sum0 = 0.f, sum1 = 0.f;
        #pragma unroll
        for (int nf = 0; nf < 8; nf++) {
            s[nf][0] = __expf(s[nf][0] - mn0); sum0 += s[nf][0];
            s[nf][1] = __expf(s[nf][1] - mn0); sum0 += s[nf][1];
            s[nf][2] = __expf(s[nf][2] - mn1); sum1 += s[nf][2];
            s[nf][3] = __expf(s[nf][3] - mn1); sum1 += s[nf][3];
        }
        sum0 += __shfl_xor_sync(0xffffffffu, sum0, 1);
        sum0 += __shfl_xor_sync(0xffffffffu, sum0, 2);
        sum1 += __shfl_xor_sync(0xffffffffu, sum1, 1);
        sum1 += __shfl_xor_sync(0xffffffffu, sum1, 2);
        l0 = l0 * corr0 + sum0;  l1 = l1 * corr1 + sum1;
        m0r = mn0;  m1r = mn1;
        #pragma unroll
        for (int nf = 0; nf < 8; nf++) {
            acc[nf][0] *= corr0; acc[nf][1] *= corr0;
            acc[nf][2] *= corr1; acc[nf][3] *= corr1;
        }

        // P -> half2 (warp-private rows)
        #pragma unroll
        for (int nf = 0; nf < 8; nf++) {
            __half2 p0 = __floats2half2_rn(s[nf][0], s[nf][1]);
            __half2 p1 = __floats2half2_rn(s[nf][2], s[nf][3]);
            sP[pr0 + nf * 4 + tid] = *(uint32_t*)&p0;
            sP[pr1 + nf * 4 + tid] = *(uint32_t*)&p1;
        }
        __syncwarp();

        // acc += P @ V  (kv = 64 -> 4 k16 steps; B from transposed V)
        #pragma unroll
        for (int ks = 0; ks < 4; ks++) {
            int kk = ks * 8;
            uint32_t a[4] = { sP[pr0 + kk + tid], sP[pr1 + kk + tid],
                              sP[pr0 + kk + tid + 4], sP[pr1 + kk + tid + 4] };
            #pragma unroll
            for (int nf = 0; nf < 8; nf++) {
                uint32_t bb[2] = { sVt[(nf * 8 + gid) * AVST + kk + tid],
                                   sVt[(nf * 8 + gid) * AVST + kk + tid + 4] };
                mma_f16(acc[nf], a, bb);
            }
        }
        __syncthreads();
    }

    float inv0 = 1.0f / l0, inv1 = 1.0f / l1;
    #pragma unroll
    for (int nf = 0; nf < 8; nf++) {
        int c = nf * 8 + 2 * tid;
        *(__half2*)(Oh + baseo + (size_t)(row0) * Dc + c) =
            __floats2half2_rn(acc[nf][0] * inv0, acc[nf][1] * inv0);
        *(__half2*)(Oh + baseo + (size_t)(row0 + 8) * Dc + c) =
            __floats2half2_rn(acc[nf][2] * inv1, acc[nf][3] * inv1);
    }
}

// ---------------------------------------------------------------------------
extern "C" void kernel_launch(void* const* d_in, const int* in_sizes, int n_in,
                              void* d_out, int out_size)
{
    const float* x   = (const float*)d_in[0];
    const float* Wq  = (const float*)d_in[1];
    const float* Wk  = (const float*)d_in[2];
    const float* Wv  = (const float*)d_in[3];
    const float* Wo  = (const float*)d_in[4];
    const float* bo  = (const float*)d_in[5];
    const float* g1  = (const float*)d_in[6];
    const float* b1  = (const float*)d_in[7];
    const float* g2  = (const float*)d_in[8];
    const float* b2  = (const float*)d_in[9];
    const float* W1  = (const float*)d_in[10];
    const float* bf1 = (const float*)d_in[11];
    const float* W2  = (const float*)d_in[12];
    const float* bf2 = (const float*)d_in[13];
    float* out = (float*)d_out;

    float *cache;
    __half *qkv, *hh, *h2h, *ctxh, *ffh, *wqkv, *wo, *w1, *w2;
    cudaGetSymbolAddress((void**)&qkv,   g_qkv);
    cudaGetSymbolAddress((void**)&cache, g_cache);
    cudaGetSymbolAddress((void**)&hh,    g_hh);
    cudaGetSymbolAddress((void**)&h2h,   g_h2h);
    cudaGetSymbolAddress((void**)&ctxh,  g_ctxh);
    cudaGetSymbolAddress((void**)&ffh,   g_ffh);
    cudaGetSymbolAddress((void**)&wqkv,  g_wqkv);
    cudaGetSymbolAddress((void**)&wo,    g_wo);
    cudaGetSymbolAddress((void**)&w1,    g_w1);
    cudaGetSymbolAddress((void**)&w2,    g_w2);

    cudaFuncSetAttribute(gemm_f16<0>, cudaFuncAttributeMaxDynamicSharedMemorySize, GSMEM);
    cudaFuncSetAttribute(gemm_f16<1>, cudaFuncAttributeMaxDynamicSharedMemorySize, GSMEM);
    cudaFuncSetAttribute(gemm_f16<2>, cudaFuncAttributeMaxDynamicSharedMemorySize, GSMEM);
    cudaFuncSetAttribute(gemm_f16<3>, cudaFuncAttributeMaxDynamicSharedMemorySize, GSMEM);
    cudaFuncSetAttribute(attn_mma_kernel, cudaFuncAttributeMaxDynamicSharedMemorySize, ATTN_SMEM);

    dim3 cb(32, 8);
    convt_kernel<<<dim3(2, 32, 16), cb>>>(Wq, wqkv,                     Dc, HDc, Dc * HDc, HDc, Dc);
    convt_kernel<<<dim3(2, 32, 16), cb>>>(Wk, wqkv + (size_t)1024 * Dc, Dc, HDc, Dc * HDc, HDc, Dc);
    convt_kernel<<<dim3(2, 32, 16), cb>>>(Wv, wqkv + (size_t)2048 * Dc, Dc, HDc, Dc * HDc, HDc, Dc);
    convt_kernel<<<dim3(32, 32, 1),  cb>>>(Wo, wo, Dc, Dc, 0, 0, Dc);
    convt_kernel<<<dim3(128, 32, 1), cb>>>(W1, w1, Dc, FFc, 0, 0, Dc);
    convt_kernel<<<dim3(32, 128, 1), cb>>>(W2, w2, FFc, Dc, 0, 0, FFc);

    // 1. LN1 -> fp16
    ln_half_kernel<<<ROWS, 256>>>(x, g1, b1, hh);

    // 2. Fused QKV projection -> qkv fp16 [ROWS][3072]
    gemm_f16<3><<<dim3(QS3 / 128, ROWS / 128), 256, GSMEM>>>(hh, wqkv, nullptr, qkv, nullptr, nullptr, ROWS, QS3, Dc);

    // 3. Attention (fp16 mma) -> ctx fp16
    attn_mma_kernel<<<dim3(Sc / 128, Hc, Bc), 256, ATTN_SMEM>>>(qkv, ctxh);

    // 4. Wo + bias + resid(x) -> cache fp32
    gemm_f16<1><<<dim3(Dc / 128, ROWS / 128), 256, GSMEM>>>(ctxh, wo, cache, nullptr, bo, x, ROWS, Dc, Dc);

    // 5. LN2 -> fp16
    ln_half_kernel<<<ROWS, 256>>>(cache, g2, b2, h2h);

    // 6. FF1 + bias + gelu -> ff fp16
    gemm_f16<2><<<dim3(FFc / 128, ROWS / 128), 256, GSMEM>>>(h2h, w1, nullptr, ffh, bf1, nullptr, ROWS, FFc, Dc);

    // 7. FF2 + bias + resid(cache) -> out fp32
    gemm_f16<1><<<dim3(Dc / 128, ROWS / 128), 256, GSMEM>>>(ffh, w2, out, nullptr, bf2, cache, ROWS, Dc, FFc);
}

// round 13
// speedup vs baseline: 1.7926x; 1.0444x over previous
#include <cuda_runtime.h>
#include <cuda_fp16.h>
#include <math.h>
#include <stdint.h>

#define Bc 8
#define Sc 512
#define Dc 1024
#define Hc 16
#define HDc 64
#define FFc 4096
#define ROWS (Bc*Sc)
#define QS3 3072

__device__ __half g_qkv[ROWS*(size_t)QS3];
__device__ float g_cache[ROWS*Dc];
__device__ __half g_hh[ROWS*Dc], g_h2h[ROWS*Dc], g_ctxh[ROWS*Dc];
__device__ __half g_ffh[ROWS*(size_t)FFc];
__device__ __half g_wqkv[(size_t)QS3*Dc];
__device__ __half g_wo[(size_t)Dc*Dc];
__device__ __half g_w1[(size_t)FFc*Dc];
__device__ __half g_w2[(size_t)Dc*FFc];

__device__ __forceinline__ uint32_t smem_u32(const void* p) {
    uint32_t a;
    asm("{ .reg .u64 t; cvta.to.shared.u64 t, %1; cvt.u32.u64 %0, t; }" : "=r"(a) : "l"(p));
    return a;
}
__device__ __forceinline__ void mma_f16(float (&d)[4], const uint32_t (&a)[4], const uint32_t (&b)[2]) {
    asm volatile("mma.sync.aligned.m16n8k16.row.col.f32.f16.f16.f32 "
        "{%0,%1,%2,%3}, {%4,%5,%6,%7}, {%8,%9}, {%0,%1,%2,%3};\n"
        : "+f"(d[0]), "+f"(d[1]), "+f"(d[2]), "+f"(d[3])
        : "r"(a[0]), "r"(a[1]), "r"(a[2]), "r"(a[3]), "r"(b[0]), "r"(b[1]));
}

// ---------------------------------------------------------------------------
// Weight convert+transpose v2: fp32 [K][N] (slice z) -> fp16 [N][K].
// 64x64 tiles, 256 threads (16x16 logical), float4 loads, 8B packed stores.
// ---------------------------------------------------------------------------
__global__ __launch_bounds__(256) void convt_kernel(
    const float* __restrict__ in, __half* __restrict__ outp,
    int K, int N, int inZ, int outZrows, int Kout)
{
    __shared__ float tile[64][65];
    int k0 = blockIdx.y * 64, n0 = blockIdx.x * 64, z = blockIdx.z;
    const float* src = in + (size_t)z * inZ;
    int tx = threadIdx.x & 15, ty = threadIdx.x >> 4;
    #pragma unroll
    for (int i = 0; i < 4; i++) {
        int kk = ty + 16 * i;
        float4 v = *(const float4*)(src + (size_t)(k0 + kk) * N + n0 + tx * 4);
        tile[kk][tx * 4 + 0] = v.x; tile[kk][tx * 4 + 1] = v.y;
        tile[kk][tx * 4 + 2] = v.z; tile[kk][tx * 4 + 3] = v.w;
    }
    __syncthreads();
    #pragma unroll
    for (int i = 0; i < 4; i++) {
        int nn = ty + 16 * i;
        __half2 h01 = __floats2half2_rn(tile[tx * 4 + 0][nn], tile[tx * 4 + 1][nn]);
        __half2 h23 = __floats2half2_rn(tile[tx * 4 + 2][nn], tile[tx * 4 + 3][nn]);
        size_t orow = (size_t)z * outZrows + n0 + nn;
        uint2 pk; pk.x = *(uint32_t*)&h01; pk.y = *(uint32_t*)&h23;
        *(uint2*)(outp + orow * Kout + k0 + tx * 4) = pk;
    }
}

// ---------------------------------------------------------------------------
// LayerNorm -> fp16
// ---------------------------------------------------------------------------
__global__ __launch_bounds__(256) void ln_half_kernel(
    const float* __restrict__ x, const float* __restrict__ gamma,
    const float* __restrict__ beta, __half* __restrict__ outp)
{
    __shared__ float red[16];
    int row = blockIdx.x;
    float4 v = ((const float4*)(x + (size_t)row * Dc))[threadIdx.x];
    float s = v.x + v.y + v.z + v.w;
    float sq = v.x*v.x + v.y*v.y + v.z*v.z + v.w*v.w;
    #pragma unroll
    for (int off = 16; off; off >>= 1) {
        s  += __shfl_xor_sync(0xffffffffu, s,  off);
        sq += __shfl_xor_sync(0xffffffffu, sq, off);
    }
    int warp = threadIdx.x >> 5, lane = threadIdx.x & 31;
    if (lane == 0) { red[warp] = s; red[8 + warp] = sq; }
    __syncthreads();
    float ts = 0.f, tsq = 0.f;
    #pragma unroll
    for (int i = 0; i < 8; i++) { ts += red[i]; tsq += red[8 + i]; }
    float mean = ts * (1.0f / Dc);
    float inv = rsqrtf(tsq * (1.0f / Dc) - mean * mean + 1e-5f);
    float4 g4 = ((const float4*)gamma)[threadIdx.x];
    float4 b4 = ((const float4*)beta )[threadIdx.x];
    __half2 o[2];
    o[0] = __floats2half2_rn((v.x-mean)*inv*g4.x + b4.x, (v.y-mean)*inv*g4.y + b4.y);
    o[1] = __floats2half2_rn((v.z-mean)*inv*g4.z + b4.z, (v.w-mean)*inv*g4.w + b4.w);
    __half2* p = (__half2*)(outp + (size_t)row * Dc) + 2 * threadIdx.x;
    p[0] = o[0]; p[1] = o[1];
}

// ---------------------------------------------------------------------------
// fp16 GEMM: 128x128, BK=32, 4-stage cp.async, 1 barrier per chunk.
// ---------------------------------------------------------------------------
#define SSTR 20
#define STGU 2560
#define STGB (STGU*4)
#define GSMEM (8 * STGB)

template<int EPI>
__global__ __launch_bounds__(256) void gemm_f16(
    const __half* __restrict__ A, const __half* __restrict__ B,
    float* __restrict__ C, __half* __restrict__ Ch,
    const float* __restrict__ bias, const float* __restrict__ resid,
    int M, int N, int K)
{
    extern __shared__ __align__(16) char smem[];
    uint32_t* sw = (uint32_t*)smem;
    const uint32_t sbase = smem_u32(smem);

    int m0 = blockIdx.y * 128, n0 = blockIdx.x * 128;
    int t = threadIdx.x;
    int w = t >> 5, lane = t & 31;
    int wm = w >> 1, wn = w & 1;
    int gid = lane >> 2, tid = lane & 3;

    float acc[2][8][4];
    #pragma unroll
    for (int mf = 0; mf < 2; mf++)
        #pragma unroll
        for (int nf = 0; nf < 8; nf++)
            #pragma unroll
            for (int c = 0; c < 4; c++) acc[mf][nf][c] = 0.f;

    auto load_stage = [&](int s, int k0) {
        #pragma unroll
        for (int i = 0; i < 2; i++) {
            int id = t + i * 256;
            int row = id >> 2, kc = id & 3;
            uint32_t sa = sbase + s * STGB + row * 80 + kc * 16;
            const __half* ga = A + (size_t)(m0 + row) * K + k0 + kc * 8;
            asm volatile("cp.async.cg.shared.global [%0], [%1], 16;" :: "r"(sa), "l"(ga));
            uint32_t sb = sbase + 4 * STGB + s * STGB + row * 80 + kc * 16;
            const __half* gb = B + (size_t)(n0 + row) * K + k0 + kc * 8;
            asm volatile("cp.async.cg.shared.global [%0], [%1], 16;" :: "r"(sb), "l"(gb));
        }
        asm volatile("cp.async.commit_group;" ::: "memory");
    };

    const int NC = K / 32;
    load_stage(0, 0);
    load_stage(1, 32);
    load_stage(2, 64);

    int s = 0;
    for (int c = 0; c < NC; c++) {
        asm volatile("cp.async.wait_group 2;" ::: "memory");
        __syncthreads();
        if (c + 3 < NC) load_stage((s + 3) & 3, (c + 3) * 32);

        uint32_t* As = sw + s * STGU;
        uint32_t* Bs = sw + 4 * STGU + s * STGU;
        #pragma unroll
        for (int ks = 0; ks < 2; ks++) {
            int kk = ks * 8;
            uint32_t afr[2][4], bfr[8][2];
            #pragma unroll
            for (int mf = 0; mf < 2; mf++) {
                int mb = wm * 32 + mf * 16 + gid;
                afr[mf][0] = As[(mb    ) * SSTR + kk + tid];
                afr[mf][1] = As[(mb + 8) * SSTR + kk + tid];
                afr[mf][2] = As[(mb    ) * SSTR + kk + tid + 4];
                afr[mf][3] = As[(mb + 8) * SSTR + kk + tid + 4];
            }
            #pragma unroll
            for (int nf = 0; nf < 8; nf++) {
                int nb = wn * 64 + nf * 8 + gid;
                bfr[nf][0] = Bs[nb * SSTR + kk + tid];
                bfr[nf][1] = Bs[nb * SSTR + kk + tid + 4];
            }
            #pragma unroll
            for (int mf = 0; mf < 2; mf++)
                #pragma unroll
                for (int nf = 0; nf < 8; nf++)
                    mma_f16(acc[mf][nf], afr[mf], bfr[nf]);
        }
        s = (s + 1) & 3;
    }

    #pragma unroll
    for (int mf = 0; mf < 2; mf++) {
        int r0 = m0 + wm * 32 + mf * 16 + gid;
        #pragma unroll
        for (int nf = 0; nf < 8; nf++) {
            int c0 = n0 + wn * 64 + nf * 8 + 2 * tid;
            float v0 = acc[mf][nf][0], v1 = acc[mf][nf][1];
            float v2 = acc[mf][nf][2], v3 = acc[mf][nf][3];
            if (EPI == 0) {
                *(float2*)(C + (size_t)r0 * N + c0)       = make_float2(v0, v1);
                *(float2*)(C + (size_t)(r0 + 8) * N + c0) = make_float2(v2, v3);
            } else if (EPI == 1) {
                float b0v = bias[c0], b1v = bias[c0 + 1];
                v0 += b0v + resid[(size_t)r0 * N + c0];
                v1 += b1v + resid[(size_t)r0 * N + c0 + 1];
                v2 += b0v + resid[(size_t)(r0 + 8) * N + c0];
                v3 += b1v + resid[(size_t)(r0 + 8) * N + c0 + 1];
                *(float2*)(C + (size_t)r0 * N + c0)       = make_float2(v0, v1);
                *(float2*)(C + (size_t)(r0 + 8) * N + c0) = make_float2(v2, v3);
            } else if (EPI == 2) {
                float b0v = bias[c0], b1v = bias[c0 + 1];
                v0 += b0v; v1 += b1v; v2 += b0v; v3 += b1v;
                v0 = 0.5f * v0 * (1.0f + erff(v0 * 0.70710678118654752f));
                v1 = 0.5f * v1 * (1.0f + erff(v1 * 0.70710678118654752f));
                v2 = 0.5f * v2 * (1.0f + erff(v2 * 0.70710678118654752f));
                v3 = 0.5f * v3 * (1.0f + erff(v3 * 0.70710678118654752f));
                *(__half2*)(Ch + (size_t)r0 * N + c0)       = __floats2half2_rn(v0, v1);
                *(__half2*)(Ch + (size_t)(r0 + 8) * N + c0) = __floats2half2_rn(v2, v3);
            } else {
                *(__half2*)(Ch + (size_t)r0 * N + c0)       = __floats2half2_rn(v0, v1);
                *(__half2*)(Ch + (size_t)(r0 + 8) * N + c0) = __floats2half2_rn(v2, v3);
            }
        }
    }
}

// ---------------------------------------------------------------------------
// Flash attention, fp16 mma + cp.async double-buffered K/V staging.
// ---------------------------------------------------------------------------
#define AV 36
#define SK_OFF   4608
#define SVR_OFF  9216
#define SVT_OFF  13824
#define SP_OFF   16128
#define ATTN_SMEM ((16128 + 4608) * 4)   // 82944 B

__global__ __launch_bounds__(256) void attn_mma_kernel(
    const __half* __restrict__ QKV, __half* __restrict__ Oh)
{
    extern __shared__ uint32_t smu[];
    const uint32_t sbase = smem_u32(smu);
    uint32_t* sQ  = smu;
    uint32_t* sVt = smu + SVT_OFF;
    uint32_t* sP  = smu + SP_OFF;

    int qt = blockIdx.x, hd = blockIdx.y, b = blockIdx.z;
    int t = threadIdx.x, w = t >> 5, lane = t & 31;
    int gid = lane >> 2, tid = lane & 3;
    size_t baseq = ((size_t)b * Sc) * QS3 + hd * HDc;
    size_t basek = baseq + 1024;
    size_t basev = baseq + 2048;
    size_t baseo = ((size_t)b * Sc) * Dc + hd * HDc;

    auto stage_kv = [&](int s, int kt) {
        #pragma unroll
        for (int i = 0; i < 2; i++) {
            int f = t + i * 256, r = f >> 3, c8 = f & 7;
            uint32_t dk = sbase + (uint32_t)(SK_OFF + s * 2304 + r * AV + c8 * 4) * 4;
            const __half* gk = QKV + basek + (size_t)(kt * 64 + r) * QS3 + c8 * 8;
            asm volatile("cp.async.cg.shared.global [%0], [%1], 16;" :: "r"(dk), "l"(gk));
            uint32_t dv = sbase + (uint32_t)(SVR_OFF + s * 2304 + r * AV + c8 * 4) * 4;
            const __half* gv = QKV + basev + (size_t)(kt * 64 + r) * QS3 + c8 * 8;
            asm volatile("cp.async.cg.shared.global [%0], [%1], 16;" :: "r"(dv), "l"(gv));
        }
        asm volatile("cp.async.commit_group;" ::: "memory");
    };

    // Q tile: 128 rows x 64 halves
    #pragma unroll
    for (int i = 0; i < 4; i++) {
        int f = t + i * 256, r = f >> 3, c8 = f & 7;
        uint4 u = *(const uint4*)(QKV + baseq + (size_t)(qt * 128 + r) * QS3 + c8 * 8);
        *(uint4*)&sQ[r * AV + c8 * 4] = u;
    }

    float m0r = -INFINITY, m1r = -INFINITY, l0 = 0.f, l1 = 0.f;
    float acc[8][4];
    #pragma unroll
    for (int nf = 0; nf < 8; nf++)
        #pragma unroll
        for (int c = 0; c < 4; c++) acc[nf][c] = 0.f;

    int row0 = qt * 128 + w * 16 + gid;
    int pr0 = (w * 16 + gid) * AV, pr1 = (w * 16 + gid + 8) * AV;
    int vrp = t & 31, vcg = (t >> 5) * 8;

    int nt = 2 * qt + 2;
    stage_kv(0, 0);
    int cur = 0;
    for (int kt = 0; kt < nt; kt++) {
        if (kt + 1 < nt) {
            stage_kv(cur ^ 1, kt + 1);
            asm volatile("cp.async.wait_group 1;" ::: "memory");
        } else {
            asm volatile("cp.async.wait_group 0;" ::: "memory");
        }
        __syncthreads();

        const uint32_t* Ks = smu + SK_OFF + cur * 2304;
        const uint32_t* Vr = smu + SVR_OFF + cur * 2304;

        {
            uint4 u0 = *(const uint4*)&Vr[(2 * vrp) * AV + (vcg >> 1)];
            uint4 u1 = *(const uint4*)&Vr[(2 * vrp + 1) * AV + (vcg >> 1)];
            const __half* h0 = (const __half*)&u0;
            const __half* h1 = (const __half*)&u1;
            #pragma unroll
            for (int i = 0; i < 8; i++) {
                __half2 hv; hv.x = h0[i]; hv.y = h1[i];
                sVt[(vcg + i) * AV + vrp] = *(uint32_t*)&hv;
            }
        }

        float s[8][4];
        #pragma unroll
        for (int nf = 0; nf < 8; nf++)
            #pragma unroll
            for (int c = 0; c < 4; c++) s[nf][c] = 0.f;
        #pragma unroll
        for (int ks = 0; ks < 4; ks++) {
            int kk = ks * 8;
            uint32_t a[4] = { sQ[pr0 + kk + tid], sQ[pr1 + kk + tid],
                              sQ[pr0 + kk + tid + 4], sQ[pr1 + kk + tid + 4] };
            #pragma unroll
            for (int nf = 0; nf < 8; nf++) {
                uint32_t bb[2] = { Ks[(nf * 8 + gid) * AV + kk + tid],
                                   Ks[(nf * 8 + gid) * AV + kk + tid + 4] };
                mma_f16(s[nf], a, bb);
            }
        }

        bool edge = (kt >= 2 * qt);
        #pragma unroll
        for (int nf = 0; nf < 8; nf++) {
            int c0 = kt * 64 + nf * 8 + 2 * tid;
            s[nf][0] *= 0.125f; s[nf][1] *= 0.125f;
            s[nf][2] *= 0.125f; s[nf][3] *= 0.125f;
            if (edge) {
                if (c0     > row0)     s[nf][0] = -1e10f;
                if (c0 + 1 > row0)     s[nf][1] = -1e10f;
                if (c0     > row0 + 8) s[nf][2] = -1e10f;
                if (c0 + 1 > row0 + 8) s[nf][3] = -1e10f;
            }
        }

        float mx0 = -INFINITY, mx1 = -INFINITY;
        #pragma unroll
        for (int nf = 0; nf < 8; nf++) {
            mx0 = fmaxf(mx0, fmaxf(s[nf][0], s[nf][1]));
            mx1 = fmaxf(mx1, fmaxf(s[nf][2], s[nf][3]));
        }
        mx0 = fmaxf(mx0, __shfl_xor_sync(0xffffffffu, mx0, 1));
        mx0 = fmaxf(mx0, __shfl_xor_sync(0xffffffffu, mx0, 2));
        mx1 = fmaxf(mx1, __shfl_xor_sync(0xffffffffu, mx1, 1));
        mx1 = fmaxf(mx1, __shfl_xor_sync(0xffffffffu, mx1, 2));
        float mn0 = fmaxf(m0r, mx0), mn1 = fmaxf(m1r, mx1);
        float corr0 = __expf(m0r - mn0), corr1 = __expf(m1r - mn1);
        float sum0 = 0.f, sum1 = 0.f;
        #pragma unroll
        for (int nf = 0; nf < 8; nf++) {
            s[nf][0] = __expf(s[nf][0] - mn0); sum0 += s[nf][0];
            s[nf][1] = __expf(s[nf][1] - mn0); sum0 += s[nf][1];
            s[nf][2] = __expf(s[nf][2] - mn1); sum1 += s[nf][2];
            s[nf][3] = __expf(s[nf][3] - mn1); sum1 += s[nf][3];
        }
        sum0 += __shfl_xor_sync(0xffffffffu, sum0, 1);
        sum0 += __shfl_xor_sync(0xffffffffu, sum0, 2);
        sum1 += __shfl_xor_sync(0xffffffffu, sum1, 1);
        sum1 += __shfl_xor_sync(0xffffffffu, sum1, 2);
        l0 = l0 * corr0 + sum0;  l1 = l1 * corr1 + sum1;
        m0r = mn0;  m1r = mn1;
        #pragma unroll
        for (int nf = 0; nf < 8; nf++) {
            acc[nf][0] *= corr0; acc[nf][1] *= corr0;
            acc[nf][2] *= corr1; acc[nf][3] *= corr1;
        }

        #pragma unroll
        for (int nf = 0; nf < 8; nf++) {
            __half2 p0 = __floats2half2_rn(s[nf][0], s[nf][1]);
            __half2 p1 = __floats2half2_rn(s[nf][2], s[nf][3]);
            sP[pr0 + nf * 4 + tid] = *(uint32_t*)&p0;
            sP[pr1 + nf * 4 + tid] = *(uint32_t*)&p1;
        }
        __syncthreads();

        #pragma unroll
        for (int ks = 0; ks < 4; ks++) {
            int kk = ks * 8;
            uint32_t a[4] = { sP[pr0 + kk + tid], sP[pr1 + kk + tid],
                              sP[pr0 + kk + tid + 4], sP[pr1 + kk + tid + 4] };
            #pragma unroll
            for (int nf = 0; nf < 8; nf++) {
                uint32_t bb[2] = { sVt[(nf * 8 + gid) * AV + kk + tid],
                                   sVt[(nf * 8 + gid) * AV + kk + tid + 4] };
                mma_f16(acc[nf], a, bb);
            }
        }
        cur ^= 1;
    }

    float inv0 = 1.0f / l0, inv1 = 1.0f / l1;
    #pragma unroll
    for (int nf = 0; nf < 8; nf++) {
        int c = nf * 8 + 2 * tid;
        *(__half2*)(Oh + baseo + (size_t)(row0) * Dc + c) =
            __floats2half2_rn(acc[nf][0] * inv0, acc[nf][1] * inv0);
        *(__half2*)(Oh + baseo + (size_t)(row0 + 8) * Dc + c) =
            __floats2half2_rn(acc[nf][2] * inv1, acc[nf][3] * inv1);
    }
}

// ---------------------------------------------------------------------------
extern "C" void kernel_launch(void* const* d_in, const int* in_sizes, int n_in,
                              void* d_out, int out_size)
{
    const float* x   = (const float*)d_in[0];
    const float* Wq  = (const float*)d_in[1];
    const float* Wk  = (const float*)d_in[2];
    const float* Wv  = (const float*)d_in[3];
    const float* Wo  = (const float*)d_in[4];
    const float* bo  = (const float*)d_in[5];
    const float* g1  = (const float*)d_in[6];
    const float* b1  = (const float*)d_in[7];
    const float* g2  = (const float*)d_in[8];
    const float* b2  = (const float*)d_in[9];
    const float* W1  = (const float*)d_in[10];
    const float* bf1 = (const float*)d_in[11];
    const float* W2  = (const float*)d_in[12];
    const float* bf2 = (const float*)d_in[13];
    float* out = (float*)d_out;

    float *cache;
    __half *qkv, *hh, *h2h, *ctxh, *ffh, *wqkv, *wo, *w1, *w2;
    cudaGetSymbolAddress((void**)&qkv,   g_qkv);
    cudaGetSymbolAddress((void**)&cache, g_cache);
    cudaGetSymbolAddress((void**)&hh,    g_hh);
    cudaGetSymbolAddress((void**)&h2h,   g_h2h);
    cudaGetSymbolAddress((void**)&ctxh,  g_ctxh);
    cudaGetSymbolAddress((void**)&ffh,   g_ffh);
    cudaGetSymbolAddress((void**)&wqkv,  g_wqkv);
    cudaGetSymbolAddress((void**)&wo,    g_wo);
    cudaGetSymbolAddress((void**)&w1,    g_w1);
    cudaGetSymbolAddress((void**)&w2,    g_w2);

    cudaFuncSetAttribute(gemm_f16<0>, cudaFuncAttributeMaxDynamicSharedMemorySize, GSMEM);
    cudaFuncSetAttribute(gemm_f16<1>, cudaFuncAttributeMaxDynamicSharedMemorySize, GSMEM);
    cudaFuncSetAttribute(gemm_f16<2>, cudaFuncAttributeMaxDynamicSharedMemorySize, GSMEM);
    cudaFuncSetAttribute(gemm_f16<3>, cudaFuncAttributeMaxDynamicSharedMemorySize, GSMEM);
    cudaFuncSetAttribute(attn_mma_kernel, cudaFuncAttributeMaxDynamicSharedMemorySize, ATTN_SMEM);

    convt_kernel<<<dim3(1, 16, 16),  256>>>(Wq, wqkv,                     Dc, HDc, Dc * HDc, HDc, Dc);
    convt_kernel<<<dim3(1, 16, 16),  256>>>(Wk, wqkv + (size_t)1024 * Dc, Dc, HDc, Dc * HDc, HDc, Dc);
    convt_kernel<<<dim3(1, 16, 16),  256>>>(Wv, wqkv + (size_t)2048 * Dc, Dc, HDc, Dc * HDc, HDc, Dc);
    convt_kernel<<<dim3(16, 16, 1),  256>>>(Wo, wo, Dc, Dc, 0, 0, Dc);
    convt_kernel<<<dim3(64, 16, 1),  256>>>(W1, w1, Dc, FFc, 0, 0, Dc);
    convt_kernel<<<dim3(16, 64, 1),  256>>>(W2, w2, FFc, Dc, 0, 0, FFc);

    ln_half_kernel<<<ROWS, 256>>>(x, g1, b1, hh);

    gemm_f16<3><<<dim3(QS3 / 128, ROWS / 128), 256, GSMEM>>>(hh, wqkv, nullptr, qkv, nullptr, nullptr, ROWS, QS3, Dc);

    attn_mma_kernel<<<dim3(Sc / 128, Hc, Bc), 256, ATTN_SMEM>>>(qkv, ctxh);

    gemm_f16<1><<<dim3(Dc / 128, ROWS / 128), 256, GSMEM>>>(ctxh, wo, cache, nullptr, bo, x, ROWS, Dc, Dc);

    ln_half_kernel<<<ROWS, 256>>>(cache, g2, b2, h2h);

    gemm_f16<2><<<dim3(FFc / 128, ROWS / 128), 256, GSMEM>>>(h2h, w1, nullptr, ffh, bf1, nullptr, ROWS, FFc, Dc);

    gemm_f16<1><<<dim3(Dc / 128, ROWS / 128), 256, GSMEM>>>(ffh, w2, out, nullptr, bf2, cache, ROWS, Dc, FFc);
}

// round 14
// speedup vs baseline: 1.8037x; 1.0062x over previous
#include <cuda_runtime.h>
#include <cuda_fp16.h>
#include <math.h>
#include <stdint.h>

#define Bc 8
#define Sc 512
#define Dc 1024
#define Hc 16
#define HDc 64
#define FFc 4096
#define ROWS (Bc*Sc)
#define QS3 3072

__device__ __half g_qkv[ROWS*(size_t)QS3];
__device__ float g_cache[ROWS*Dc];
__device__ __half g_hh[ROWS*Dc], g_h2h[ROWS*Dc], g_ctxh[ROWS*Dc];
__device__ __half g_ffh[ROWS*(size_t)FFc];
__device__ __half g_wqkv[(size_t)QS3*Dc];
__device__ __half g_wo[(size_t)Dc*Dc];
__device__ __half g_w1[(size_t)FFc*Dc];
__device__ __half g_w2[(size_t)Dc*FFc];

__device__ __forceinline__ uint32_t smem_u32(const void* p) {
    uint32_t a;
    asm("{ .reg .u64 t; cvta.to.shared.u64 t, %1; cvt.u32.u64 %0, t; }" : "=r"(a) : "l"(p));
    return a;
}
__device__ __forceinline__ void mma_f16(float (&d)[4], const uint32_t (&a)[4], const uint32_t (&b)[2]) {
    asm volatile("mma.sync.aligned.m16n8k16.row.col.f32.f16.f16.f32 "
        "{%0,%1,%2,%3}, {%4,%5,%6,%7}, {%8,%9}, {%0,%1,%2,%3};\n"
        : "+f"(d[0]), "+f"(d[1]), "+f"(d[2]), "+f"(d[3])
        : "r"(a[0]), "r"(a[1]), "r"(a[2]), "r"(a[3]), "r"(b[0]), "r"(b[1]));
}
__device__ __forceinline__ void ldsm4(uint32_t& r0, uint32_t& r1, uint32_t& r2, uint32_t& r3, uint32_t addr) {
    asm volatile("ldmatrix.sync.aligned.m8n8.x4.shared.b16 {%0,%1,%2,%3}, [%4];"
        : "=r"(r0), "=r"(r1), "=r"(r2), "=r"(r3) : "r"(addr));
}

// ---------------------------------------------------------------------------
// Weight convert+transpose: fp32 [K][N] (slice z) -> fp16 [N][K]
// ---------------------------------------------------------------------------
__global__ __launch_bounds__(256) void convt_kernel(
    const float* __restrict__ in, __half* __restrict__ outp,
    int K, int N, int inZ, int outZrows, int Kout)
{
    __shared__ float tile[64][65];
    int k0 = blockIdx.y * 64, n0 = blockIdx.x * 64, z = blockIdx.z;
    const float* src = in + (size_t)z * inZ;
    int tx = threadIdx.x & 15, ty = threadIdx.x >> 4;
    #pragma unroll
    for (int i = 0; i < 4; i++) {
        int kk = ty + 16 * i;
        float4 v = *(const float4*)(src + (size_t)(k0 + kk) * N + n0 + tx * 4);
        tile[kk][tx * 4 + 0] = v.x; tile[kk][tx * 4 + 1] = v.y;
        tile[kk][tx * 4 + 2] = v.z; tile[kk][tx * 4 + 3] = v.w;
    }
    __syncthreads();
    #pragma unroll
    for (int i = 0; i < 4; i++) {
        int nn = ty + 16 * i;
        __half2 h01 = __floats2half2_rn(tile[tx * 4 + 0][nn], tile[tx * 4 + 1][nn]);
        __half2 h23 = __floats2half2_rn(tile[tx * 4 + 2][nn], tile[tx * 4 + 3][nn]);
        size_t orow = (size_t)z * outZrows + n0 + nn;
        uint2 pk; pk.x = *(uint32_t*)&h01; pk.y = *(uint32_t*)&h23;
        *(uint2*)(outp + orow * Kout + k0 + tx * 4) = pk;
    }
}

// ---------------------------------------------------------------------------
// LayerNorm -> fp16
// ---------------------------------------------------------------------------
__global__ __launch_bounds__(256) void ln_half_kernel(
    const float* __restrict__ x, const float* __restrict__ gamma,
    const float* __restrict__ beta, __half* __restrict__ outp)
{
    __shared__ float red[16];
    int row = blockIdx.x;
    float4 v = ((const float4*)(x + (size_t)row * Dc))[threadIdx.x];
    float s = v.x + v.y + v.z + v.w;
    float sq = v.x*v.x + v.y*v.y + v.z*v.z + v.w*v.w;
    #pragma unroll
    for (int off = 16; off; off >>= 1) {
        s  += __shfl_xor_sync(0xffffffffu, s,  off);
        sq += __shfl_xor_sync(0xffffffffu, sq, off);
    }
    int warp = threadIdx.x >> 5, lane = threadIdx.x & 31;
    if (lane == 0) { red[warp] = s; red[8 + warp] = sq; }
    __syncthreads();
    float ts = 0.f, tsq = 0.f;
    #pragma unroll
    for (int i = 0; i < 8; i++) { ts += red[i]; tsq += red[8 + i]; }
    float mean = ts * (1.0f / Dc);
    float inv = rsqrtf(tsq * (1.0f / Dc) - mean * mean + 1e-5f);
    float4 g4 = ((const float4*)gamma)[threadIdx.x];
    float4 b4 = ((const float4*)beta )[threadIdx.x];
    __half2 o[2];
    o[0] = __floats2half2_rn((v.x-mean)*inv*g4.x + b4.x, (v.y-mean)*inv*g4.y + b4.y);
    o[1] = __floats2half2_rn((v.z-mean)*inv*g4.z + b4.z, (v.w-mean)*inv*g4.w + b4.w);
    __half2* p = (__half2*)(outp + (size_t)row * Dc) + 2 * threadIdx.x;
    p[0] = o[0]; p[1] = o[1];
}

// ---------------------------------------------------------------------------
// fp16 GEMM: 128x128, BK=32, 4-stage cp.async, 1 barrier/chunk, ldmatrix frags.
// ---------------------------------------------------------------------------
#define SSTR 20
#define STGU 2560
#define STGB (STGU*4)
#define GSMEM (8 * STGB)

template<int EPI>
__global__ __launch_bounds__(256) void gemm_f16(
    const __half* __restrict__ A, const __half* __restrict__ B,
    float* __restrict__ C, __half* __restrict__ Ch,
    const float* __restrict__ bias, const float* __restrict__ resid,
    int M, int N, int K)
{
    extern __shared__ __align__(16) char smem[];
    const uint32_t sbase = smem_u32(smem);

    int m0 = blockIdx.y * 128, n0 = blockIdx.x * 128;
    int t = threadIdx.x;
    int w = t >> 5, lane = t & 31;
    int wm = w >> 1, wn = w & 1;
    int gid = lane >> 2, tid = lane & 3;

    float acc[2][8][4];
    #pragma unroll
    for (int mf = 0; mf < 2; mf++)
        #pragma unroll
        for (int nf = 0; nf < 8; nf++)
            #pragma unroll
            for (int c = 0; c < 4; c++) acc[mf][nf][c] = 0.f;

    auto load_stage = [&](int s, int k0) {
        #pragma unroll
        for (int i = 0; i < 2; i++) {
            int id = t + i * 256;
            int row = id >> 2, kc = id & 3;
            uint32_t sa = sbase + s * STGB + row * 80 + kc * 16;
            const __half* ga = A + (size_t)(m0 + row) * K + k0 + kc * 8;
            asm volatile("cp.async.cg.shared.global [%0], [%1], 16;" :: "r"(sa), "l"(ga));
            uint32_t sb = sbase + 4 * STGB + s * STGB + row * 80 + kc * 16;
            const __half* gb = B + (size_t)(n0 + row) * K + k0 + kc * 8;
            asm volatile("cp.async.cg.shared.global [%0], [%1], 16;" :: "r"(sb), "l"(gb));
        }
        asm volatile("cp.async.commit_group;" ::: "memory");
    };

    // ldmatrix per-lane source coords (word units within a stage buffer)
    int lrow = (lane & 7) + ((lane >> 3) & 1) * 8;   // row within 16-row frag group
    int lcol = ((lane >> 4) & 1) * 4;                // word offset: k-halves 0-7 / 8-15
    int aRowBase = wm * 32 + lrow;                   // + mf*16
    int bRowBase = wn * 64 + lrow;                   // + nf2*16

    const int NC = K / 32;
    load_stage(0, 0);
    load_stage(1, 32);
    load_stage(2, 64);

    int s = 0;
    for (int c = 0; c < NC; c++) {
        asm volatile("cp.async.wait_group 2;" ::: "memory");
        __syncthreads();
        if (c + 3 < NC) load_stage((s + 3) & 3, (c + 3) * 32);

        uint32_t aST = sbase + s * STGB;
        uint32_t bST = sbase + 4 * STGB + s * STGB;
        #pragma unroll
        for (int ks = 0; ks < 2; ks++) {
            int kk = ks * 8;
            uint32_t afr[2][4], bfr[8][2];
            #pragma unroll
            for (int mf = 0; mf < 2; mf++) {
                uint32_t addr = aST + (uint32_t)((aRowBase + mf * 16) * SSTR + kk + lcol) * 4;
                ldsm4(afr[mf][0], afr[mf][1], afr[mf][2], afr[mf][3], addr);
            }
            #pragma unroll
            for (int nf2 = 0; nf2 < 4; nf2++) {
                uint32_t r0, r1, r2, r3;
                uint32_t addr = bST + (uint32_t)((bRowBase + nf2 * 16) * SSTR + kk + lcol) * 4;
                ldsm4(r0, r1, r2, r3, addr);
                bfr[2 * nf2][0] = r0;  bfr[2 * nf2][1] = r2;
                bfr[2 * nf2 + 1][0] = r1;  bfr[2 * nf2 + 1][1] = r3;
            }
            #pragma unroll
            for (int mf = 0; mf < 2; mf++)
                #pragma unroll
                for (int nf = 0; nf < 8; nf++)
                    mma_f16(acc[mf][nf], afr[mf], bfr[nf]);
        }
        s = (s + 1) & 3;
    }

    #pragma unroll
    for (int mf = 0; mf < 2; mf++) {
        int r0 = m0 + wm * 32 + mf * 16 + gid;
        #pragma unroll
        for (int nf = 0; nf < 8; nf++) {
            int c0 = n0 + wn * 64 + nf * 8 + 2 * tid;
            float v0 = acc[mf][nf][0], v1 = acc[mf][nf][1];
            float v2 = acc[mf][nf][2], v3 = acc[mf][nf][3];
            if (EPI == 0) {
                *(float2*)(C + (size_t)r0 * N + c0)       = make_float2(v0, v1);
                *(float2*)(C + (size_t)(r0 + 8) * N + c0) = make_float2(v2, v3);
            } else if (EPI == 1) {
                float b0v = bias[c0], b1v = bias[c0 + 1];
                v0 += b0v + resid[(size_t)r0 * N + c0];
                v1 += b1v + resid[(size_t)r0 * N + c0 + 1];
                v2 += b0v + resid[(size_t)(r0 + 8) * N + c0];
                v3 += b1v + resid[(size_t)(r0 + 8) * N + c0 + 1];
                *(float2*)(C + (size_t)r0 * N + c0)       = make_float2(v0, v1);
                *(float2*)(C + (size_t)(r0 + 8) * N + c0) = make_float2(v2, v3);
            } else if (EPI == 2) {
                float b0v = bias[c0], b1v = bias[c0 + 1];
                v0 += b0v; v1 += b1v; v2 += b0v; v3 += b1v;
                v0 = 0.5f * v0 * (1.0f + erff(v0 * 0.70710678118654752f));
                v1 = 0.5f * v1 * (1.0f + erff(v1 * 0.70710678118654752f));
                v2 = 0.5f * v2 * (1.0f + erff(v2 * 0.70710678118654752f));
                v3 = 0.5f * v3 * (1.0f + erff(v3 * 0.70710678118654752f));
                *(__half2*)(Ch + (size_t)r0 * N + c0)       = __floats2half2_rn(v0, v1);
                *(__half2*)(Ch + (size_t)(r0 + 8) * N + c0) = __floats2half2_rn(v2, v3);
            } else {
                *(__half2*)(Ch + (size_t)r0 * N + c0)       = __floats2half2_rn(v0, v1);
                *(__half2*)(Ch + (size_t)(r0 + 8) * N + c0) = __floats2half2_rn(v2, v3);
            }
        }
    }
}

// ---------------------------------------------------------------------------
// Flash attention, fp16 mma + cp.async double-buffered K/V staging (unchanged).
// ---------------------------------------------------------------------------
#define AV 36
#define SK_OFF   4608
#define SVR_OFF  9216
#define SVT_OFF  13824
#define SP_OFF   16128
#define ATTN_SMEM ((16128 + 4608) * 4)   // 82944 B

__global__ __launch_bounds__(256) void attn_mma_kernel(
    const __half* __restrict__ QKV, __half* __restrict__ Oh)
{
    extern __shared__ uint32_t smu[];
    const uint32_t sbase = smem_u32(smu);
    uint32_t* sQ  = smu;
    uint32_t* sVt = smu + SVT_OFF;
    uint32_t* sP  = smu + SP_OFF;

    int qt = blockIdx.x, hd = blockIdx.y, b = blockIdx.z;
    int t = threadIdx.x, w = t >> 5, lane = t & 31;
    int gid = lane >> 2, tid = lane & 3;
    size_t baseq = ((size_t)b * Sc) * QS3 + hd * HDc;
    size_t basek = baseq + 1024;
    size_t basev = baseq + 2048;
    size_t baseo = ((size_t)b * Sc) * Dc + hd * HDc;

    auto stage_kv = [&](int s, int kt) {
        #pragma unroll
        for (int i = 0; i < 2; i++) {
            int f = t + i * 256, r = f >> 3, c8 = f & 7;
            uint32_t dk = sbase + (uint32_t)(SK_OFF + s * 2304 + r * AV + c8 * 4) * 4;
            const __half* gk = QKV + basek + (size_t)(kt * 64 + r) * QS3 + c8 * 8;
            asm volatile("cp.async.cg.shared.global [%0], [%1], 16;" :: "r"(dk), "l"(gk));
            uint32_t dv = sbase + (uint32_t)(SVR_OFF + s * 2304 + r * AV + c8 * 4) * 4;
            const __half* gv = QKV + basev + (size_t)(kt * 64 + r) * QS3 + c8 * 8;
            asm volatile("cp.async.cg.shared.global [%0], [%1], 16;" :: "r"(dv), "l"(gv));
        }
        asm volatile("cp.async.commit_group;" ::: "memory");
    };

    #pragma unroll
    for (int i = 0; i < 4; i++) {
        int f = t + i * 256, r = f >> 3, c8 = f & 7;
        uint4 u = *(const uint4*)(QKV + baseq + (size_t)(qt * 128 + r) * QS3 + c8 * 8);
        *(uint4*)&sQ[r * AV + c8 * 4] = u;
    }

    float m0r = -INFINITY, m1r = -INFINITY, l0 = 0.f, l1 = 0.f;
    float acc[8][4];
    #pragma unroll
    for (int nf = 0; nf < 8; nf++)
        #pragma unroll
        for (int c = 0; c < 4; c++) acc[nf][c] = 0.f;

    int row0 = qt * 128 + w * 16 + gid;
    int pr0 = (w * 16 + gid) * AV, pr1 = (w * 16 + gid + 8) * AV;
    int vrp = t & 31, vcg = (t >> 5) * 8;

    int nt = 2 * qt + 2;
    stage_kv(0, 0);
    int cur = 0;
    for (int kt = 0; kt < nt; kt++) {
        if (kt + 1 < nt) {
            stage_kv(cur ^ 1, kt + 1);
            asm volatile("cp.async.wait_group 1;" ::: "memory");
        } else {
            asm volatile("cp.async.wait_group 0;" ::: "memory");
        }
        __syncthreads();

        const uint32_t* Ks = smu + SK_OFF + cur * 2304;
        const uint32_t* Vr = smu + SVR_OFF + cur * 2304;

        {
            uint4 u0 = *(const uint4*)&Vr[(2 * vrp) * AV + (vcg >> 1)];
            uint4 u1 = *(const uint4*)&Vr[(2 * vrp + 1) * AV + (vcg >> 1)];
            const __half* h0 = (const __half*)&u0;
            const __half* h1 = (const __half*)&u1;
            #pragma unroll
            for (int i = 0; i < 8; i++) {
                __half2 hv; hv.x = h0[i]; hv.y = h1[i];
                sVt[(vcg + i) * AV + vrp] = *(uint32_t*)&hv;
            }
        }

        float s[8][4];
        #pragma unroll
        for (int nf = 0; nf < 8; nf++)
            #pragma unroll
            for (int c = 0; c < 4; c++) s[nf][c] = 0.f;
        #pragma unroll
        for (int ks = 0; ks < 4; ks++) {
            int kk = ks * 8;
            uint32_t a[4] = { sQ[pr0 + kk + tid], sQ[pr1 + kk + tid],
                              sQ[pr0 + kk + tid + 4], sQ[pr1 + kk + tid + 4] };
            #pragma unroll
            for (int nf = 0; nf < 8; nf++) {
                uint32_t bb[2] = { Ks[(nf * 8 + gid) * AV + kk + tid],
                                   Ks[(nf * 8 + gid) * AV + kk + tid + 4] };
                mma_f16(s[nf], a, bb);
            }
        }

        bool edge = (kt >= 2 * qt);
        #pragma unroll
        for (int nf = 0; nf < 8; nf++) {
            int c0 = kt * 64 + nf * 8 + 2 * tid;
            s[nf][0] *= 0.125f; s[nf][1] *= 0.125f;
            s[nf][2] *= 0.125f; s[nf][3] *= 0.125f;
            if (edge) {
                if (c0     > row0)     s[nf][0] = -1e10f;
                if (c0 + 1 > row0)     s[nf][1] = -1e10f;
                if (c0     > row0 + 8) s[nf][2] = -1e10f;
                if (c0 + 1 > row0 + 8) s[nf][3] = -1e10f;
            }
        }

        float mx0 = -INFINITY, mx1 = -INFINITY;
        #pragma unroll
        for (int nf = 0; nf < 8; nf++) {
            mx0 = fmaxf(mx0, fmaxf(s[nf][0], s[nf][1]));
            mx1 = fmaxf(mx1, fmaxf(s[nf][2], s[nf][3]));
        }
        mx0 = fmaxf(mx0, __shfl_xor_sync(0xffffffffu, mx0, 1));
        mx0 = fmaxf(mx0, __shfl_xor_sync(0xffffffffu, mx0, 2));
        mx1 = fmaxf(mx1, __shfl_xor_sync(0xffffffffu, mx1, 1));
        mx1 = fmaxf(mx1, __shfl_xor_sync(0xffffffffu, mx1, 2));
        float mn0 = fmaxf(m0r, mx0), mn1 = fmaxf(m1r, mx1);
        float corr0 = __expf(m0r - mn0), corr1 = __expf(m1r - mn1);
        float sum0 = 0.f, sum1 = 0.f;
        #pragma unroll
        for (int nf = 0; nf < 8; nf++) {
            s[nf][0] = __expf(s[nf][0] - mn0); sum0 += s[nf][0];
            s[nf][1] = __expf(s[nf][1] - mn0); sum0 += s[nf][1];
            s[nf][2] = __expf(s[nf][2] - mn1); sum1 += s[nf][2];
            s[nf][3] = __expf(s[nf][3] - mn1); sum1 += s[nf][3];
        }
        sum0 += __shfl_xor_sync(0xffffffffu, sum0, 1);
        sum0 += __shfl_xor_sync(0xffffffffu, sum0, 2);
        sum1 += __shfl_xor_sync(0xffffffffu, sum1, 1);
        sum1 += __shfl_xor_sync(0xffffffffu, sum1, 2);
        l0 = l0 * corr0 + sum0;  l1 = l1 * corr1 + sum1;
        m0r = mn0;  m1r = mn1;
        #pragma unroll
        for (int nf = 0; nf < 8; nf++) {
            acc[nf][0] *= corr0; acc[nf][1] *= corr0;
            acc[nf][2] *= corr1; acc[nf][3] *= corr1;
        }

        #pragma unroll
        for (int nf = 0; nf < 8; nf++) {
            __half2 p0 = __floats2half2_rn(s[nf][0], s[nf][1]);
            __half2 p1 = __floats2half2_rn(s[nf][2], s[nf][3]);
            sP[pr0 + nf * 4 + tid] = *(uint32_t*)&p0;
            sP[pr1 + nf * 4 + tid] = *(uint32_t*)&p1;
        }
        __syncthreads();

        #pragma unroll
        for (int ks = 0; ks < 4; ks++) {
            int kk = ks * 8;
            uint32_t a[4] = { sP[pr0 + kk + tid], sP[pr1 + kk + tid],
                              sP[pr0 + kk + tid + 4], sP[pr1 + kk + tid + 4] };
            #pragma unroll
            for (int nf = 0; nf < 8; nf++) {
                uint32_t bb[2] = { sVt[(nf * 8 + gid) * AV + kk + tid],
                                   sVt[(nf * 8 + gid) * AV + kk + tid + 4] };
                mma_f16(acc[nf], a, bb);
            }
        }
        cur ^= 1;
    }

    float inv0 = 1.0f / l0, inv1 = 1.0f / l1;
    #pragma unroll
    for (int nf = 0; nf < 8; nf++) {
        int c = nf * 8 + 2 * tid;
        *(__half2*)(Oh + baseo + (size_t)(row0) * Dc + c) =
            __floats2half2_rn(acc[nf][0] * inv0, acc[nf][1] * inv0);
        *(__half2*)(Oh + baseo + (size_t)(row0 + 8) * Dc + c) =
            __floats2half2_rn(acc[nf][2] * inv1, acc[nf][3] * inv1);
    }
}

// ---------------------------------------------------------------------------
extern "C" void kernel_launch(void* const* d_in, const int* in_sizes, int n_in,
                              void* d_out, int out_size)
{
    const float* x   = (const float*)d_in[0];
    const float* Wq  = (const float*)d_in[1];
    const float* Wk  = (const float*)d_in[2];
    const float* Wv  = (const float*)d_in[3];
    const float* Wo  = (const float*)d_in[4];
    const float* bo  = (const float*)d_in[5];
    const float* g1  = (const float*)d_in[6];
    const float* b1  = (const float*)d_in[7];
    const float* g2  = (const float*)d_in[8];
    const float* b2  = (const float*)d_in[9];
    const float* W1  = (const float*)d_in[10];
    const float* bf1 = (const float*)d_in[11];
    const float* W2  = (const float*)d_in[12];
    const float* bf2 = (const float*)d_in[13];
    float* out = (float*)d_out;

    float *cache;
    __half *qkv, *hh, *h2h, *ctxh, *ffh, *wqkv, *wo, *w1, *w2;
    cudaGetSymbolAddress((void**)&qkv,   g_qkv);
    cudaGetSymbolAddress((void**)&cache, g_cache);
    cudaGetSymbolAddress((void**)&hh,    g_hh);
    cudaGetSymbolAddress((void**)&h2h,   g_h2h);
    cudaGetSymbolAddress((void**)&ctxh,  g_ctxh);
    cudaGetSymbolAddress((void**)&ffh,   g_ffh);
    cudaGetSymbolAddress((void**)&wqkv,  g_wqkv);
    cudaGetSymbolAddress((void**)&wo,    g_wo);
    cudaGetSymbolAddress((void**)&w1,    g_w1);
    cudaGetSymbolAddress((void**)&w2,    g_w2);

    cudaFuncSetAttribute(gemm_f16<0>, cudaFuncAttributeMaxDynamicSharedMemorySize, GSMEM);
    cudaFuncSetAttribute(gemm_f16<1>, cudaFuncAttributeMaxDynamicSharedMemorySize, GSMEM);
    cudaFuncSetAttribute(gemm_f16<2>, cudaFuncAttributeMaxDynamicSharedMemorySize, GSMEM);
    cudaFuncSetAttribute(gemm_f16<3>, cudaFuncAttributeMaxDynamicSharedMemorySize, GSMEM);
    cudaFuncSetAttribute(attn_mma_kernel, cudaFuncAttributeMaxDynamicSharedMemorySize, ATTN_SMEM);

    convt_kernel<<<dim3(1, 16, 16),  256>>>(Wq, wqkv,                     Dc, HDc, Dc * HDc, HDc, Dc);
    convt_kernel<<<dim3(1, 16, 16),  256>>>(Wk, wqkv + (size_t)1024 * Dc, Dc, HDc, Dc * HDc, HDc, Dc);
    convt_kernel<<<dim3(1, 16, 16),  256>>>(Wv, wqkv + (size_t)2048 * Dc, Dc, HDc, Dc * HDc, HDc, Dc);
    convt_kernel<<<dim3(16, 16, 1),  256>>>(Wo, wo, Dc, Dc, 0, 0, Dc);
    convt_kernel<<<dim3(64, 16, 1),  256>>>(W1, w1, Dc, FFc, 0, 0, Dc);
    convt_kernel<<<dim3(16, 64, 1),  256>>>(W2, w2, FFc, Dc, 0, 0, FFc);

    ln_half_kernel<<<ROWS, 256>>>(x, g1, b1, hh);

    gemm_f16<3><<<dim3(QS3 / 128, ROWS / 128), 256, GSMEM>>>(hh, wqkv, nullptr, qkv, nullptr, nullptr, ROWS, QS3, Dc);

    attn_mma_kernel<<<dim3(Sc / 128, Hc, Bc), 256, ATTN_SMEM>>>(qkv, ctxh);

    gemm_f16<1><<<dim3(Dc / 128, ROWS / 128), 256, GSMEM>>>(ctxh, wo, cache, nullptr, bo, x, ROWS, Dc, Dc);

    ln_half_kernel<<<ROWS, 256>>>(cache, g2, b2, h2h);

    gemm_f16<2><<<dim3(FFc / 128, ROWS / 128), 256, GSMEM>>>(h2h, w1, nullptr, ffh, bf1, nullptr, ROWS, FFc, Dc);

    gemm_f16<1><<<dim3(Dc / 128, ROWS / 128), 256, GSMEM>>>(ffh, w2, out, nullptr, bf2, cache, ROWS, Dc, FFc);
}